// round 10
// baseline (speedup 1.0000x reference)
#include <cuda_runtime.h>
#include <cuda_fp16.h>
#include <math.h>

// ---------------------------------------------------------------------------
// Problem constants
// ---------------------------------------------------------------------------
#define N_NOTES   64
#define N_WORDS   256
#define BATCH     32
#define WDIM      128
#define OC        256
#define HID       256

// Output layout (float32)
#define OFF_NORM 1048576
#define OFF_VEC  1050624
#define OFF_FIN  1067008

// ---------------------------------------------------------------------------
// Scratch (device globals)
// ---------------------------------------------------------------------------
__device__ unsigned int g_featmax[N_NOTES * BATCH * OC];
__device__ float        g_gi[2 * N_NOTES * BATCH * 3 * HID];
__device__ float        g_WT[512 * 512];
__device__ float        g_attn[N_NOTES * BATCH];
// B repacked per term/n-half: [term][nhalf][k=384][col=136 halfs]
__device__ __half       g_Bp[2][2][384][136];

// ---------------------------------------------------------------------------
// PTX helpers (mma.sync path — tcgen05 NOT supported by this ptxas target)
// ---------------------------------------------------------------------------
__device__ __forceinline__ void ldm_x4(unsigned* r, unsigned addr) {
    asm volatile("ldmatrix.sync.aligned.m8n8.x4.shared.b16 {%0,%1,%2,%3},[%4];"
        : "=r"(r[0]), "=r"(r[1]), "=r"(r[2]), "=r"(r[3]) : "r"(addr));
}
__device__ __forceinline__ void ldm_x4t(unsigned* r, unsigned addr) {
    asm volatile("ldmatrix.sync.aligned.m8n8.x4.trans.shared.b16 {%0,%1,%2,%3},[%4];"
        : "=r"(r[0]), "=r"(r[1]), "=r"(r[2]), "=r"(r[3]) : "r"(addr));
}
__device__ __forceinline__ void mma16816(float* c, const unsigned* a, const unsigned* b) {
    asm volatile("mma.sync.aligned.m16n8k16.row.col.f32.f16.f16.f32 "
        "{%0,%1,%2,%3},{%4,%5,%6,%7},{%8,%9},{%0,%1,%2,%3};"
        : "+f"(c[0]), "+f"(c[1]), "+f"(c[2]), "+f"(c[3])
        : "r"(a[0]), "r"(a[1]), "r"(a[2]), "r"(a[3]), "r"(b[0]), "r"(b[1]));
}
__device__ __forceinline__ void cp16(unsigned dst, const void* src) {
    asm volatile("cp.async.cg.shared.global [%0],[%1],16;" :: "r"(dst), "l"(src));
}
__device__ __forceinline__ void cp_commit() { asm volatile("cp.async.commit_group;"); }
template<int N> __device__ __forceinline__ void cp_wait() {
    asm volatile("cp.async.wait_group %0;" :: "n"(N));
}
__device__ __forceinline__ unsigned enc_key(float m) {
    unsigned bits = __float_as_uint(m);
    return (bits & 0x80000000u) ? ~bits : (bits | 0x80000000u);
}

// ---------------------------------------------------------------------------
// Kernel 0a: reset featmax keys
// ---------------------------------------------------------------------------
__global__ void init_featmax_kernel() {
    g_featmax[blockIdx.x * 256 + threadIdx.x] = 0u;
}

// ---------------------------------------------------------------------------
// Kernel 0b: conv_w[oc][k] -> fp16 hi + hi*2^-8 images, repacked [term][nh][k][136]
// ---------------------------------------------------------------------------
__global__ void __launch_bounds__(256) wsplit_kernel(const float* __restrict__ conv_w) {
    const int k = blockIdx.x;          // 0..383
    const int n = threadIdx.x;         // 0..255
    const float v = conv_w[n * 384 + k];
    const __half hi = __float2half(v);
    g_Bp[0][n >> 7][k][n & 127] = hi;
    g_Bp[1][n >> 7][k][n & 127] = __float2half(__half2float(hi) * 0.00390625f);
}

// ---------------------------------------------------------------------------
// Kernel 1: conv as 2-term fp16 HMMA GEMM; CTA = (sample, l-half, n-half).
// 256 threads, M=128 x N=128 per CTA, warp tile m32 x n64 (8 warps, 4m x 2n).
// 2 CTAs/SM. half==1 CTAs also do the l=256,257 tail for their n-half.
//   z = ahi*bhi + ((a-ahi)*2^8)*(bhi*2^-8)
// ---------------------------------------------------------------------------
#define ES      136        // E row stride (halfs)
#define EROWS   132
#define BSH     136        // B row stride (halfs)
#define BCH     8704       // B chunk bytes = 32 * 136 * 2
#define EHI_OFF 0
#define ELO_OFF 35904
#define BHI_OFF 71808      // 2 stages x 8704
#define BLO_OFF 89216      // 2 stages x 8704
#define WMAX_OFF 106624    // 4 x 128 floats
#define TOK_OFF  108672    // 132 ints
#define CONV_SMEM 109312

__global__ void __launch_bounds__(256, 2) conv_mma_kernel(
    const int*   __restrict__ mini_batch,   // [64][256][32]
    const float* __restrict__ embed,        // [50000][128]
    const float* __restrict__ conv_w)       // [256][384]
{
    extern __shared__ char sm[];
    const unsigned smu = (unsigned)__cvta_generic_to_shared(sm);
    const int tid = threadIdx.x, lane = tid & 31, w = tid >> 5;
    const int mg = w >> 1;         // 0..3 (m block of 32 rows)
    const int ng = w & 1;          // 0..1 (n block of 64 cols)
    const int sample = blockIdx.x >> 2;
    const int half   = (blockIdx.x >> 1) & 1;
    const int nh     = blockIdx.x & 1;
    const int l0     = half << 7;
    const int n = sample >> 5, b = sample & 31;

    int* tok = (int*)(sm + TOK_OFF);
    const char* srcH = (const char*)&g_Bp[0][nh][0][0];
    const char* srcL = (const char*)&g_Bp[1][nh][0][0];

    // prefetch B chunks 0,1
    for (int i = tid; i < BCH / 16; i += 256) {
        cp16(smu + BHI_OFF + i * 16, srcH + i * 16);
        cp16(smu + BLO_OFF + i * 16, srcL + i * 16);
    }
    cp_commit();
    for (int i = tid; i < BCH / 16; i += 256) {
        cp16(smu + BHI_OFF + BCH + i * 16, srcH + BCH + i * 16);
        cp16(smu + BLO_OFF + BCH + i * 16, srcL + BCH + i * 16);
    }
    cp_commit();

    if (tid < EROWS) {
        const int word = l0 + tid - 2;
        tok[tid] = (word >= 0 && word < N_WORDS)
                 ? mini_batch[(n * N_WORDS + word) * BATCH + b] : -1;
    }
    __syncthreads();

    // ---- build E hi / lo' ----
    for (int i = tid; i < EROWS * 32; i += 256) {
        const int row = i >> 5, q = i & 31;
        const int t = tok[row];
        float4 v;
        if (t >= 0) v = *(const float4*)(embed + (size_t)t * WDIM + q * 4);
        else        v = make_float4(0.f, 0.f, 0.f, 0.f);
        const __half h0 = __float2half(v.x), h1 = __float2half(v.y);
        const __half h2 = __float2half(v.z), h3 = __float2half(v.w);
        __half2 hp0 = __halves2half2(h0, h1);
        __half2 hp1 = __halves2half2(h2, h3);
        __half2 lp0 = __halves2half2(
            __float2half((v.x - __half2float(h0)) * 256.0f),
            __float2half((v.y - __half2float(h1)) * 256.0f));
        __half2 lp1 = __halves2half2(
            __float2half((v.z - __half2float(h2)) * 256.0f),
            __float2half((v.w - __half2float(h3)) * 256.0f));
        const unsigned off = (unsigned)(row * ES + q * 4) * 2;
        *(uint2*)(sm + EHI_OFF + off) = make_uint2(*(unsigned*)&hp0, *(unsigned*)&hp1);
        *(uint2*)(sm + ELO_OFF + off) = make_uint2(*(unsigned*)&lp0, *(unsigned*)&lp1);
    }

    float cm[2][8][4];
#pragma unroll
    for (int i = 0; i < 2; i++)
#pragma unroll
        for (int j = 0; j < 8; j++)
#pragma unroll
            for (int r = 0; r < 4; r++) cm[i][j][r] = 0.0f;
    __syncthreads();

    // ---- main loop: 12 k-chunks of 32 ----
    for (int c = 0; c < 12; c++) {
        const int stage = c & 1;
        if (c < 11) cp_wait<1>(); else cp_wait<0>();
        __syncthreads();

#pragma unroll
        for (int h = 0; h < 2; h++) {
            const int k0 = c * 32 + h * 16;
            const int seg = k0 >> 7, kk = k0 & 127;
            const unsigned acol = kk + ((lane >> 4) << 3);
            unsigned ahi[2][4], alo[2][4];
#pragma unroll
            for (int mt = 0; mt < 2; mt++) {
                const unsigned aoff =
                    ((mg * 32 + mt * 16 + (lane & 15) + seg) * ES + acol) * 2;
                ldm_x4(ahi[mt], smu + EHI_OFF + aoff);
                ldm_x4(alo[mt], smu + ELO_OFF + aoff);
            }
            const unsigned brow = (h << 4) + (lane & 15);
#pragma unroll
            for (int nn = 0; nn < 4; nn++) {
                const unsigned bcol = ng * 64 + nn * 16 + ((lane >> 4) << 3);
                const unsigned boff = stage * BCH + brow * (BSH * 2) + bcol * 2;
                unsigned bh[4], bl[4];
                ldm_x4t(bh, smu + BHI_OFF + boff);
                ldm_x4t(bl, smu + BLO_OFF + boff);
#pragma unroll
                for (int mt = 0; mt < 2; mt++) {
                    mma16816(cm[mt][nn * 2],     ahi[mt], bh);
                    mma16816(cm[mt][nn * 2 + 1], ahi[mt], bh + 2);
                    mma16816(cm[mt][nn * 2],     alo[mt], bl);
                    mma16816(cm[mt][nn * 2 + 1], alo[mt], bl + 2);
                }
            }
        }
        __syncthreads();
        if (c + 2 < 12) {
            const int coff = (c + 2) * BCH;
            for (int i = tid; i < BCH / 16; i += 256) {
                cp16(smu + BHI_OFF + stage * BCH + i * 16, srcH + coff + i * 16);
                cp16(smu + BLO_OFF + stage * BCH + i * 16, srcL + coff + i * 16);
            }
            cp_commit();
        }
    }

    // ---- fused max-pool over M (=l), per column (within this n-half) ----
    float* wmax = (float*)(sm + WMAX_OFF);
#pragma unroll
    for (int t = 0; t < 8; t++) {
        float m0 = fmaxf(fmaxf(cm[0][t][0], cm[0][t][2]),
                         fmaxf(cm[1][t][0], cm[1][t][2]));
        float m1 = fmaxf(fmaxf(cm[0][t][1], cm[0][t][3]),
                         fmaxf(cm[1][t][1], cm[1][t][3]));
#pragma unroll
        for (int off = 4; off < 32; off <<= 1) {
            m0 = fmaxf(m0, __shfl_xor_sync(0xffffffffu, m0, off));
            m1 = fmaxf(m1, __shfl_xor_sync(0xffffffffu, m1, off));
        }
        if (lane < 4) {
            const int col = ng * 64 + (t >> 1) * 16 + (t & 1) * 8 + lane * 2;
            wmax[mg * 128 + col]     = m0;
            wmax[mg * 128 + col + 1] = m1;
        }
    }
    __syncthreads();
    if (tid < 128) {
        const float m = fmaxf(fmaxf(wmax[tid], wmax[128 + tid]),
                              fmaxf(wmax[256 + tid], wmax[384 + tid]));
        atomicMax(&g_featmax[sample * 256 + nh * 128 + tid], enc_key(m));
    }

    // ---- tail rows l=256,257 (half==1 only), this CTA's n-half ----
    if (half == 1) {
        const int l_idx = tid >> 7;            // 0 -> l=256, 1 -> l=257
        const int oc = nh * 128 + (tid & 127);
        const __half* e254 = (const __half*)(sm + EHI_OFF) + 128 * ES;  // word 254
        const __half* e255 = (const __half*)(sm + EHI_OFF) + 129 * ES;  // word 255
        const float* W = conv_w + oc * 384;
        float acc = 0.0f;
        if (l_idx == 0) {
#pragma unroll 8
            for (int d = 0; d < 128; d += 2) {
                const float2 w0 = *(const float2*)(W + d);
                const float2 w1 = *(const float2*)(W + 128 + d);
                const float2 ea = __half22float2(*(const __half2*)(e254 + d));
                const float2 eb = __half22float2(*(const __half2*)(e255 + d));
                acc += w0.x * ea.x + w0.y * ea.y + w1.x * eb.x + w1.y * eb.y;
            }
        } else {
#pragma unroll 8
            for (int d = 0; d < 128; d += 2) {
                const float2 w0 = *(const float2*)(W + d);
                const float2 eb = __half22float2(*(const __half2*)(e255 + d));
                acc += w0.x * eb.x + w0.y * eb.y;
            }
        }
        atomicMax(&g_featmax[sample * 256 + oc], enc_key(acc));
    }
}

// ---------------------------------------------------------------------------
// Kernel 2: gi = feat @ w_ih^T + b_ih (feat decoded: tanh(conv_b + max))
// ---------------------------------------------------------------------------
__global__ void __launch_bounds__(256) gi_kernel(
    const float* __restrict__ w_ih_f, const float* __restrict__ w_ih_b,
    const float* __restrict__ b_ih_f, const float* __restrict__ b_ih_b,
    const float* __restrict__ conv_b)
{
    __shared__ float As[BATCH * OC];
    const int tid = threadIdx.x;
    const int dir = blockIdx.x >> 6;
    const int n   = blockIdx.x & 63;

    for (int i = tid; i < BATCH * OC; i += 256) {
        const unsigned key = g_featmax[(n * BATCH + (i >> 8)) * 256 + (i & 255)];
        const unsigned bits = (key & 0x80000000u) ? (key & 0x7fffffffu) : ~key;
        As[i] = tanhf(conv_b[i & 255] + __uint_as_float(bits));
    }

    const float* W  = dir ? w_ih_b : w_ih_f;
    const float* bi = dir ? b_ih_b : b_ih_f;
    const float* w0 = W + (tid      ) * OC;
    const float* w1 = W + (tid + 256) * OC;
    const float* w2 = W + (tid + 512) * OC;

    float acc0[32], acc1[32], acc2[32];
#pragma unroll
    for (int bb = 0; bb < 32; bb++) { acc0[bb] = 0.f; acc1[bb] = 0.f; acc2[bb] = 0.f; }
    __syncthreads();

    for (int k4 = 0; k4 < OC / 4; k4++) {
        const float4 v0 = *(const float4*)(w0 + k4 * 4);
        const float4 v1 = *(const float4*)(w1 + k4 * 4);
        const float4 v2 = *(const float4*)(w2 + k4 * 4);
#pragma unroll
        for (int bb = 0; bb < 32; bb++) {
            const float4 a = *(const float4*)&As[bb * OC + k4 * 4];
            acc0[bb] += v0.x * a.x + v0.y * a.y + v0.z * a.z + v0.w * a.w;
            acc1[bb] += v1.x * a.x + v1.y * a.y + v1.z * a.z + v1.w * a.w;
            acc2[bb] += v2.x * a.x + v2.y * a.y + v2.z * a.z + v2.w * a.w;
        }
    }
    const float bi0 = bi[tid], bi1 = bi[tid + 256], bi2 = bi[tid + 512];
    float* go = g_gi + (size_t)((dir * N_NOTES + n) * BATCH) * 768;
#pragma unroll 4
    for (int bb = 0; bb < 32; bb++) {
        go[bb * 768 +       tid] = acc0[bb] + bi0;
        go[bb * 768 + 256 + tid] = acc1[bb] + bi1;
        go[bb * 768 + 512 + tid] = acc2[bb] + bi2;
    }
}

// ---------------------------------------------------------------------------
// Kernel 3: GRU recurrence. CTA = (dir, b).
// ---------------------------------------------------------------------------
__global__ void __launch_bounds__(256) gru_kernel(
    const float* __restrict__ w_hh_f, const float* __restrict__ w_hh_b,
    const float* __restrict__ b_hh_f, const float* __restrict__ b_hh_b,
    const float* __restrict__ hidden_state,
    float* __restrict__ out)
{
    __shared__ float h[HID];
    const int i   = threadIdx.x;
    const int dir = blockIdx.x >> 5;
    const int b   = blockIdx.x & 31;

    const float* whh = dir ? w_hh_b : w_hh_f;
    const float* bhh = dir ? b_hh_b : b_hh_f;

    h[i] = hidden_state[(dir * BATCH + b) * HID + i];
    const float bh0 = bhh[i], bh1 = bhh[i + 256], bh2 = bhh[i + 512];
    const float* w0 = whh + (i      ) * HID;
    const float* w1 = whh + (i + 256) * HID;
    const float* w2 = whh + (i + 512) * HID;
    __syncthreads();

    for (int s = 0; s < N_NOTES; s++) {
        const int n = dir ? (N_NOTES - 1 - s) : s;
        float g0 = bh0, g1 = bh1, g2 = bh2;
#pragma unroll 4
        for (int k4 = 0; k4 < HID / 4; k4++) {
            const float4 hv = *(const float4*)&h[k4 * 4];
            const float4 a = *(const float4*)(w0 + k4 * 4);
            const float4 c = *(const float4*)(w1 + k4 * 4);
            const float4 e = *(const float4*)(w2 + k4 * 4);
            g0 += a.x * hv.x + a.y * hv.y + a.z * hv.z + a.w * hv.w;
            g1 += c.x * hv.x + c.y * hv.y + c.z * hv.z + c.w * hv.w;
            g2 += e.x * hv.x + e.y * hv.y + e.z * hv.z + e.w * hv.w;
        }
        const float* gp = g_gi + (size_t)((dir * N_NOTES + n) * BATCH + b) * 768;
        const float r  = 1.0f / (1.0f + expf(-(gp[i]       + g0)));
        const float z  = 1.0f / (1.0f + expf(-(gp[i + 256] + g1)));
        const float nn = tanhf(gp[i + 512] + r * g2);
        const float hn = (1.0f - z) * nn + z * h[i];
        __syncthreads();
        h[i] = hn;
        __syncthreads();
        out[(size_t)(n * BATCH + b) * 512 + dir * HID + i] = hn;
    }
}

// ---------------------------------------------------------------------------
// Kernel 4a: transpose W_note -> g_WT[e][d]
// ---------------------------------------------------------------------------
__global__ void __launch_bounds__(256) wnote_transpose_kernel(const float* __restrict__ W)
{
    const int e = blockIdx.x;
    for (int d = threadIdx.x; d < 512; d += 256)
        g_WT[e * 512 + d] = W[d * 512 + e];
}

// ---------------------------------------------------------------------------
// Kernel 4b: additive attention scores
// ---------------------------------------------------------------------------
__global__ void __launch_bounds__(256) attn_kernel(
    const float* __restrict__ out_note,
    const float* __restrict__ bias_note,
    const float* __restrict__ proj_note)
{
    extern __shared__ float As[];
    __shared__ float wred[8][32];
    const int tid = threadIdx.x;
    const int n = blockIdx.x;

    const float* src = out_note + (size_t)n * BATCH * 512;
    for (int i = tid; i < (BATCH * 512) / 4; i += 256)
        ((float4*)As)[i] = ((const float4*)src)[i];

    float attnacc[32];
#pragma unroll
    for (int bb = 0; bb < 32; bb++) attnacc[bb] = 0.0f;
    __syncthreads();

    for (int ee = 0; ee < 2; ee++) {
        const int e = ee * 256 + tid;
        const float* w = g_WT + e * 512;
        float acc[32];
#pragma unroll
        for (int bb = 0; bb < 32; bb++) acc[bb] = 0.0f;
        for (int d4 = 0; d4 < 128; d4++) {
            const float4 wv = *(const float4*)(w + d4 * 4);
#pragma unroll
            for (int bb = 0; bb < 32; bb++) {
                const float4 a = *(const float4*)&As[bb * 512 + d4 * 4];
                acc[bb] += wv.x * a.x + wv.y * a.y + wv.z * a.z + wv.w * a.w;
            }
        }
        const float be = bias_note[e], pe = proj_note[e];
#pragma unroll
        for (int bb = 0; bb < 32; bb++)
            attnacc[bb] += tanhf(acc[bb] + be) * pe;
    }
#pragma unroll
    for (int off = 16; off; off >>= 1)
#pragma unroll
        for (int bb = 0; bb < 32; bb++)
            attnacc[bb] += __shfl_xor_sync(0xffffffffu, attnacc[bb], off);
    const int wid = tid >> 5, lane = tid & 31;
    if (lane == 0)
#pragma unroll
        for (int bb = 0; bb < 32; bb++) wred[wid][bb] = attnacc[bb];
    __syncthreads();
    if (tid < 32) {
        float s = 0.0f;
#pragma unroll
        for (int w = 0; w < 8; w++) s += wred[w][tid];
        g_attn[n * BATCH + tid] = s;
    }
}

// ---------------------------------------------------------------------------
// Kernel 5: softmax + weighted sum + final linear. CTA per b.
// ---------------------------------------------------------------------------
__global__ void __launch_bounds__(256) final_kernel(
    const float* __restrict__ out_note,
    const float* __restrict__ lin_w,
    const float* __restrict__ lin_b,
    float* __restrict__ out)
{
    __shared__ float sa[64];
    __shared__ float vec[512];
    __shared__ float stats[2];
    const int tid = threadIdx.x;
    const int b = blockIdx.x;

    if (tid < 64) sa[tid] = g_attn[tid * BATCH + b];
    __syncthreads();
    if (tid < 32) {
        const float v0 = sa[tid], v1 = sa[tid + 32];
        float m = fmaxf(v0, v1);
#pragma unroll
        for (int o = 16; o; o >>= 1) m = fmaxf(m, __shfl_xor_sync(0xffffffffu, m, o));
        float s = expf(v0 - m) + expf(v1 - m);
#pragma unroll
        for (int o = 16; o; o >>= 1) s += __shfl_xor_sync(0xffffffffu, s, o);
        if (tid == 0) { stats[0] = m; stats[1] = s; }
    }
    __syncthreads();
    if (tid < 64) {
        const float nv = expf(sa[tid] - stats[0]) / stats[1];
        sa[tid] = nv;
        out[OFF_NORM + b * 64 + tid] = nv;
    }
    __syncthreads();
#pragma unroll
    for (int dd = 0; dd < 2; dd++) {
        const int d = dd * 256 + tid;
        float acc = 0.0f;
#pragma unroll 8
        for (int n = 0; n < 64; n++)
            acc += sa[n] * out_note[(size_t)(n * BATCH + b) * 512 + d];
        vec[d] = acc;
        out[OFF_VEC + b * 512 + d] = acc;
    }
    __syncthreads();
    if (tid < 64) {
        const int c = tid >> 5, lane = tid & 31;
        float p = 0.0f;
#pragma unroll 4
        for (int i = lane; i < 512; i += 32) p += lin_w[c * 512 + i] * vec[i];
#pragma unroll
        for (int o = 16; o; o >>= 1) p += __shfl_xor_sync(0xffffffffu, p, o);
        if (lane == 0) out[OFF_FIN + b * 2 + c] = p + lin_b[c];
    }
}

// ---------------------------------------------------------------------------
// Launcher (conv_mma is the 4th launch so the profiler captures it)
// ---------------------------------------------------------------------------
extern "C" void kernel_launch(void* const* d_in, const int* in_sizes, int n_in,
                              void* d_out, int out_size)
{
    (void)in_sizes; (void)n_in; (void)out_size;
    const int*   mini_batch = (const int*)d_in[0];
    const float* hidden     = (const float*)d_in[1];
    const float* embed      = (const float*)d_in[2];
    const float* conv_w     = (const float*)d_in[3];
    const float* conv_b     = (const float*)d_in[4];
    const float* w_ih_f     = (const float*)d_in[5];
    const float* w_hh_f     = (const float*)d_in[6];
    const float* b_ih_f     = (const float*)d_in[7];
    const float* b_hh_f     = (const float*)d_in[8];
    const float* w_ih_b     = (const float*)d_in[9];
    const float* w_hh_b     = (const float*)d_in[10];
    const float* b_ih_b     = (const float*)d_in[11];
    const float* b_hh_b     = (const float*)d_in[12];
    const float* W_note     = (const float*)d_in[13];
    const float* bias_note  = (const float*)d_in[14];
    const float* proj_note  = (const float*)d_in[15];
    const float* lin_w      = (const float*)d_in[16];
    const float* lin_b      = (const float*)d_in[17];
    float* out = (float*)d_out;

    cudaFuncSetAttribute(conv_mma_kernel,
                         cudaFuncAttributeMaxDynamicSharedMemorySize, CONV_SMEM);
    cudaFuncSetAttribute(attn_kernel,
                         cudaFuncAttributeMaxDynamicSharedMemorySize, 65536);

    init_featmax_kernel<<<N_NOTES * BATCH, 256>>>();
    wsplit_kernel<<<384, 256>>>(conv_w);
    wnote_transpose_kernel<<<512, 256>>>(W_note);
    conv_mma_kernel<<<N_NOTES * BATCH * 4, 256, CONV_SMEM>>>(mini_batch, embed, conv_w);
    gi_kernel<<<128, 256>>>(w_ih_f, w_ih_b, b_ih_f, b_ih_b, conv_b);
    gru_kernel<<<64, 256>>>(w_hh_f, w_hh_b, b_hh_f, b_hh_b, hidden, out);
    attn_kernel<<<64, 256, 65536>>>(out, bias_note, proj_note);
    final_kernel<<<32, 256>>>(out, lin_w, lin_b, out);
}

// round 11
// speedup vs baseline: 1.4539x; 1.4539x over previous
#include <cuda_runtime.h>
#include <cuda_fp16.h>
#include <math.h>

// ---------------------------------------------------------------------------
// Problem constants
// ---------------------------------------------------------------------------
#define N_NOTES   64
#define N_WORDS   256
#define BATCH     32
#define WDIM      128
#define OC        256
#define HID       256

// Output layout (float32)
#define OFF_NORM 1048576
#define OFF_VEC  1050624
#define OFF_FIN  1067008

// ---------------------------------------------------------------------------
// Scratch (device globals)
// ---------------------------------------------------------------------------
__device__ unsigned int g_featmax[N_NOTES * BATCH * OC];
__device__ float        g_gi[2 * N_NOTES * BATCH * 3 * HID];
__device__ float        g_attn[N_NOTES * BATCH];
// conv W repacked per term/n-half: [term][nhalf][k=384][col=136 halfs]
__device__ __half       g_Bp[2][2][384][136];
// GRU weights, coalesced: [dir][(gate*64+k4)*256 + n] = float4 over k
__device__ float4       g_Wth[2 * 49152];   // w_hh
__device__ float4       g_Wti[2 * 49152];   // w_ih
// W_note coalesced: [d4*512 + e] = float4 over d
__device__ float4       g_WAp[65536];

// ---------------------------------------------------------------------------
// PTX helpers (mma.sync path — tcgen05 NOT supported by this ptxas target)
// ---------------------------------------------------------------------------
__device__ __forceinline__ void ldm_x4(unsigned* r, unsigned addr) {
    asm volatile("ldmatrix.sync.aligned.m8n8.x4.shared.b16 {%0,%1,%2,%3},[%4];"
        : "=r"(r[0]), "=r"(r[1]), "=r"(r[2]), "=r"(r[3]) : "r"(addr));
}
__device__ __forceinline__ void ldm_x4t(unsigned* r, unsigned addr) {
    asm volatile("ldmatrix.sync.aligned.m8n8.x4.trans.shared.b16 {%0,%1,%2,%3},[%4];"
        : "=r"(r[0]), "=r"(r[1]), "=r"(r[2]), "=r"(r[3]) : "r"(addr));
}
__device__ __forceinline__ void mma16816(float* c, const unsigned* a, const unsigned* b) {
    asm volatile("mma.sync.aligned.m16n8k16.row.col.f32.f16.f16.f32 "
        "{%0,%1,%2,%3},{%4,%5,%6,%7},{%8,%9},{%0,%1,%2,%3};"
        : "+f"(c[0]), "+f"(c[1]), "+f"(c[2]), "+f"(c[3])
        : "r"(a[0]), "r"(a[1]), "r"(a[2]), "r"(a[3]), "r"(b[0]), "r"(b[1]));
}
__device__ __forceinline__ void cp16(unsigned dst, const void* src) {
    asm volatile("cp.async.cg.shared.global [%0],[%1],16;" :: "r"(dst), "l"(src));
}
__device__ __forceinline__ void cp_commit() { asm volatile("cp.async.commit_group;"); }
template<int N> __device__ __forceinline__ void cp_wait() {
    asm volatile("cp.async.wait_group %0;" :: "n"(N));
}
__device__ __forceinline__ unsigned enc_key(float m) {
    unsigned bits = __float_as_uint(m);
    return (bits & 0x80000000u) ? ~bits : (bits | 0x80000000u);
}

// ---------------------------------------------------------------------------
// Kernel 0: fused prep — featmax init, conv-W split, w_hh/w_ih/W_note repack.
// grid = 2048, 256 threads.
// ---------------------------------------------------------------------------
__global__ void __launch_bounds__(256) prep_kernel(
    const float* __restrict__ conv_w,
    const float* __restrict__ w_hh_f, const float* __restrict__ w_hh_b,
    const float* __restrict__ w_ih_f, const float* __restrict__ w_ih_b,
    const float* __restrict__ W_note)
{
    const int blk = blockIdx.x, tid = threadIdx.x;
    g_featmax[blk * 256 + tid] = 0u;

    if (blk < 384) {
        // conv W: fp16 hi + hi*2^-8, repacked [term][nh][k][128]
        const int k = blk, n = tid;
        const float v = conv_w[n * 384 + k];
        const __half hi = __float2half(v);
        g_Bp[0][n >> 7][k][n & 127] = hi;
        g_Bp[1][n >> 7][k][n & 127] = __float2half(__half2float(hi) * 0.00390625f);
    } else if (blk < 1152) {
        // w_hh then w_ih: [dir][(gate*64+k4)*256+n] = W[(gate*256+n)*256 + k4*4 .. +3]
        const int idx = (blk - 384) * 256 + tid;     // 0..196607
        const int which = idx / 98304;               // 0: hh, 1: ih
        const int r = idx % 98304;
        const int n = r & 255, k4 = (r >> 8) & 63, gd = r >> 14;  // gd 0..5
        const int dir = gd / 3, gate = gd % 3;
        const float* W = which ? (dir ? w_ih_b : w_ih_f)
                               : (dir ? w_hh_b : w_hh_f);
        const float* src = W + (gate * 256 + n) * 256 + k4 * 4;
        const float4 v = make_float4(src[0], src[1], src[2], src[3]);
        float4* dst = which ? g_Wti : g_Wth;
        dst[dir * 49152 + (gate * 64 + k4) * 256 + n] = v;
    } else if (blk < 1408) {
        // W_note: [d4*512 + e] = W[(d4*4+j)*512 + e]
        const int idx = (blk - 1152) * 256 + tid;    // 0..65535
        const int e = idx & 511, d4 = idx >> 9;
        g_WAp[d4 * 512 + e] = make_float4(
            W_note[(d4 * 4 + 0) * 512 + e], W_note[(d4 * 4 + 1) * 512 + e],
            W_note[(d4 * 4 + 2) * 512 + e], W_note[(d4 * 4 + 3) * 512 + e]);
    }
}

// ---------------------------------------------------------------------------
// Kernel 1: conv as 2-term fp16 HMMA GEMM; CTA = (sample, l-half, n-half).
// (unchanged from R10: measured 905 us, tensor 37.4%)
// ---------------------------------------------------------------------------
#define ES      136
#define EROWS   132
#define BSH     136
#define BCH     8704
#define EHI_OFF 0
#define ELO_OFF 35904
#define BHI_OFF 71808
#define BLO_OFF 89216
#define WMAX_OFF 106624
#define TOK_OFF  108672
#define CONV_SMEM 109312

__global__ void __launch_bounds__(256, 2) conv_mma_kernel(
    const int*   __restrict__ mini_batch,
    const float* __restrict__ embed,
    const float* __restrict__ conv_w)
{
    extern __shared__ char sm[];
    const unsigned smu = (unsigned)__cvta_generic_to_shared(sm);
    const int tid = threadIdx.x, lane = tid & 31, w = tid >> 5;
    const int mg = w >> 1;
    const int ng = w & 1;
    const int sample = blockIdx.x >> 2;
    const int half   = (blockIdx.x >> 1) & 1;
    const int nh     = blockIdx.x & 1;
    const int l0     = half << 7;
    const int n = sample >> 5, b = sample & 31;

    int* tok = (int*)(sm + TOK_OFF);
    const char* srcH = (const char*)&g_Bp[0][nh][0][0];
    const char* srcL = (const char*)&g_Bp[1][nh][0][0];

    for (int i = tid; i < BCH / 16; i += 256) {
        cp16(smu + BHI_OFF + i * 16, srcH + i * 16);
        cp16(smu + BLO_OFF + i * 16, srcL + i * 16);
    }
    cp_commit();
    for (int i = tid; i < BCH / 16; i += 256) {
        cp16(smu + BHI_OFF + BCH + i * 16, srcH + BCH + i * 16);
        cp16(smu + BLO_OFF + BCH + i * 16, srcL + BCH + i * 16);
    }
    cp_commit();

    if (tid < EROWS) {
        const int word = l0 + tid - 2;
        tok[tid] = (word >= 0 && word < N_WORDS)
                 ? mini_batch[(n * N_WORDS + word) * BATCH + b] : -1;
    }
    __syncthreads();

    for (int i = tid; i < EROWS * 32; i += 256) {
        const int row = i >> 5, q = i & 31;
        const int t = tok[row];
        float4 v;
        if (t >= 0) v = *(const float4*)(embed + (size_t)t * WDIM + q * 4);
        else        v = make_float4(0.f, 0.f, 0.f, 0.f);
        const __half h0 = __float2half(v.x), h1 = __float2half(v.y);
        const __half h2 = __float2half(v.z), h3 = __float2half(v.w);
        __half2 hp0 = __halves2half2(h0, h1);
        __half2 hp1 = __halves2half2(h2, h3);
        __half2 lp0 = __halves2half2(
            __float2half((v.x - __half2float(h0)) * 256.0f),
            __float2half((v.y - __half2float(h1)) * 256.0f));
        __half2 lp1 = __halves2half2(
            __float2half((v.z - __half2float(h2)) * 256.0f),
            __float2half((v.w - __half2float(h3)) * 256.0f));
        const unsigned off = (unsigned)(row * ES + q * 4) * 2;
        *(uint2*)(sm + EHI_OFF + off) = make_uint2(*(unsigned*)&hp0, *(unsigned*)&hp1);
        *(uint2*)(sm + ELO_OFF + off) = make_uint2(*(unsigned*)&lp0, *(unsigned*)&lp1);
    }

    float cm[2][8][4];
#pragma unroll
    for (int i = 0; i < 2; i++)
#pragma unroll
        for (int j = 0; j < 8; j++)
#pragma unroll
            for (int r = 0; r < 4; r++) cm[i][j][r] = 0.0f;
    __syncthreads();

    for (int c = 0; c < 12; c++) {
        const int stage = c & 1;
        if (c < 11) cp_wait<1>(); else cp_wait<0>();
        __syncthreads();

#pragma unroll
        for (int h = 0; h < 2; h++) {
            const int k0 = c * 32 + h * 16;
            const int seg = k0 >> 7, kk = k0 & 127;
            const unsigned acol = kk + ((lane >> 4) << 3);
            unsigned ahi[2][4], alo[2][4];
#pragma unroll
            for (int mt = 0; mt < 2; mt++) {
                const unsigned aoff =
                    ((mg * 32 + mt * 16 + (lane & 15) + seg) * ES + acol) * 2;
                ldm_x4(ahi[mt], smu + EHI_OFF + aoff);
                ldm_x4(alo[mt], smu + ELO_OFF + aoff);
            }
            const unsigned brow = (h << 4) + (lane & 15);
#pragma unroll
            for (int nn = 0; nn < 4; nn++) {
                const unsigned bcol = ng * 64 + nn * 16 + ((lane >> 4) << 3);
                const unsigned boff = stage * BCH + brow * (BSH * 2) + bcol * 2;
                unsigned bh[4], bl[4];
                ldm_x4t(bh, smu + BHI_OFF + boff);
                ldm_x4t(bl, smu + BLO_OFF + boff);
#pragma unroll
                for (int mt = 0; mt < 2; mt++) {
                    mma16816(cm[mt][nn * 2],     ahi[mt], bh);
                    mma16816(cm[mt][nn * 2 + 1], ahi[mt], bh + 2);
                    mma16816(cm[mt][nn * 2],     alo[mt], bl);
                    mma16816(cm[mt][nn * 2 + 1], alo[mt], bl + 2);
                }
            }
        }
        __syncthreads();
        if (c + 2 < 12) {
            const int coff = (c + 2) * BCH;
            for (int i = tid; i < BCH / 16; i += 256) {
                cp16(smu + BHI_OFF + stage * BCH + i * 16, srcH + coff + i * 16);
                cp16(smu + BLO_OFF + stage * BCH + i * 16, srcL + coff + i * 16);
            }
            cp_commit();
        }
    }

    float* wmax = (float*)(sm + WMAX_OFF);
#pragma unroll
    for (int t = 0; t < 8; t++) {
        float m0 = fmaxf(fmaxf(cm[0][t][0], cm[0][t][2]),
                         fmaxf(cm[1][t][0], cm[1][t][2]));
        float m1 = fmaxf(fmaxf(cm[0][t][1], cm[0][t][3]),
                         fmaxf(cm[1][t][1], cm[1][t][3]));
#pragma unroll
        for (int off = 4; off < 32; off <<= 1) {
            m0 = fmaxf(m0, __shfl_xor_sync(0xffffffffu, m0, off));
            m1 = fmaxf(m1, __shfl_xor_sync(0xffffffffu, m1, off));
        }
        if (lane < 4) {
            const int col = ng * 64 + (t >> 1) * 16 + (t & 1) * 8 + lane * 2;
            wmax[mg * 128 + col]     = m0;
            wmax[mg * 128 + col + 1] = m1;
        }
    }
    __syncthreads();
    if (tid < 128) {
        const float m = fmaxf(fmaxf(wmax[tid], wmax[128 + tid]),
                              fmaxf(wmax[256 + tid], wmax[384 + tid]));
        atomicMax(&g_featmax[sample * 256 + nh * 128 + tid], enc_key(m));
    }

    if (half == 1) {
        const int l_idx = tid >> 7;
        const int oc = nh * 128 + (tid & 127);
        const __half* e254 = (const __half*)(sm + EHI_OFF) + 128 * ES;
        const __half* e255 = (const __half*)(sm + EHI_OFF) + 129 * ES;
        const float* W = conv_w + oc * 384;
        float acc = 0.0f;
        if (l_idx == 0) {
#pragma unroll 8
            for (int d = 0; d < 128; d += 2) {
                const float2 w0 = *(const float2*)(W + d);
                const float2 w1 = *(const float2*)(W + 128 + d);
                const float2 ea = __half22float2(*(const __half2*)(e254 + d));
                const float2 eb = __half22float2(*(const __half2*)(e255 + d));
                acc += w0.x * ea.x + w0.y * ea.y + w1.x * eb.x + w1.y * eb.y;
            }
        } else {
#pragma unroll 8
            for (int d = 0; d < 128; d += 2) {
                const float2 w0 = *(const float2*)(W + d);
                const float2 eb = __half22float2(*(const __half2*)(e255 + d));
                acc += w0.x * eb.x + w0.y * eb.y;
            }
        }
        atomicMax(&g_featmax[sample * 256 + oc], enc_key(acc));
    }
}

// ---------------------------------------------------------------------------
// Kernel 2: gi = feat @ w_ih^T + b_ih — COALESCED weights (g_Wti)
// ---------------------------------------------------------------------------
__global__ void __launch_bounds__(256) gi_kernel(
    const float* __restrict__ b_ih_f, const float* __restrict__ b_ih_b,
    const float* __restrict__ conv_b)
{
    __shared__ float As[BATCH * OC];
    const int tid = threadIdx.x;
    const int dir = blockIdx.x >> 6;
    const int n   = blockIdx.x & 63;

    for (int i = tid; i < BATCH * OC; i += 256) {
        const unsigned key = g_featmax[(n * BATCH + (i >> 8)) * 256 + (i & 255)];
        const unsigned bits = (key & 0x80000000u) ? (key & 0x7fffffffu) : ~key;
        As[i] = tanhf(conv_b[i & 255] + __uint_as_float(bits));
    }

    const float* bi = dir ? b_ih_b : b_ih_f;
    const float4* W0 = g_Wti + dir * 49152 + tid;      // + k4*256
    const float4* W1 = W0 + 64 * 256;
    const float4* W2 = W0 + 128 * 256;

    float acc0[32], acc1[32], acc2[32];
#pragma unroll
    for (int bb = 0; bb < 32; bb++) { acc0[bb] = 0.f; acc1[bb] = 0.f; acc2[bb] = 0.f; }
    __syncthreads();

    for (int k4 = 0; k4 < OC / 4; k4++) {
        const float4 v0 = W0[k4 * 256];
        const float4 v1 = W1[k4 * 256];
        const float4 v2 = W2[k4 * 256];
#pragma unroll
        for (int bb = 0; bb < 32; bb++) {
            const float4 a = *(const float4*)&As[bb * OC + k4 * 4];
            acc0[bb] += v0.x * a.x + v0.y * a.y + v0.z * a.z + v0.w * a.w;
            acc1[bb] += v1.x * a.x + v1.y * a.y + v1.z * a.z + v1.w * a.w;
            acc2[bb] += v2.x * a.x + v2.y * a.y + v2.z * a.z + v2.w * a.w;
        }
    }
    const float bi0 = bi[tid], bi1 = bi[tid + 256], bi2 = bi[tid + 512];
    float* go = g_gi + (size_t)((dir * N_NOTES + n) * BATCH) * 768;
#pragma unroll 4
    for (int bb = 0; bb < 32; bb++) {
        go[bb * 768 +       tid] = acc0[bb] + bi0;
        go[bb * 768 + 256 + tid] = acc1[bb] + bi1;
        go[bb * 768 + 512 + tid] = acc2[bb] + bi2;
    }
}

// ---------------------------------------------------------------------------
// Kernel 3: GRU recurrence — COALESCED weights (g_Wth). CTA = (dir, b).
// ---------------------------------------------------------------------------
__global__ void __launch_bounds__(256) gru_kernel(
    const float* __restrict__ b_hh_f, const float* __restrict__ b_hh_b,
    const float* __restrict__ hidden_state,
    float* __restrict__ out)
{
    __shared__ float h[HID];
    const int i   = threadIdx.x;
    const int dir = blockIdx.x >> 5;
    const int b   = blockIdx.x & 31;

    const float* bhh = dir ? b_hh_b : b_hh_f;
    const float4* W0 = g_Wth + dir * 49152 + i;        // + k4*256
    const float4* W1 = W0 + 64 * 256;
    const float4* W2 = W0 + 128 * 256;

    h[i] = hidden_state[(dir * BATCH + b) * HID + i];
    const float bh0 = bhh[i], bh1 = bhh[i + 256], bh2 = bhh[i + 512];
    __syncthreads();

    for (int s = 0; s < N_NOTES; s++) {
        const int n = dir ? (N_NOTES - 1 - s) : s;
        float g0 = bh0, g1 = bh1, g2 = bh2;
#pragma unroll 4
        for (int k4 = 0; k4 < HID / 4; k4++) {
            const float4 hv = *(const float4*)&h[k4 * 4];
            const float4 a = W0[k4 * 256];
            const float4 c = W1[k4 * 256];
            const float4 e = W2[k4 * 256];
            g0 += a.x * hv.x + a.y * hv.y + a.z * hv.z + a.w * hv.w;
            g1 += c.x * hv.x + c.y * hv.y + c.z * hv.z + c.w * hv.w;
            g2 += e.x * hv.x + e.y * hv.y + e.z * hv.z + e.w * hv.w;
        }
        const float* gp = g_gi + (size_t)((dir * N_NOTES + n) * BATCH + b) * 768;
        const float r  = 1.0f / (1.0f + expf(-(gp[i]       + g0)));
        const float z  = 1.0f / (1.0f + expf(-(gp[i + 256] + g1)));
        const float nn = tanhf(gp[i + 512] + r * g2);
        const float hn = (1.0f - z) * nn + z * h[i];
        __syncthreads();
        h[i] = hn;
        __syncthreads();
        out[(size_t)(n * BATCH + b) * 512 + dir * HID + i] = hn;
    }
}

// ---------------------------------------------------------------------------
// Kernel 4: additive attention scores — COALESCED W_note (g_WAp)
// ---------------------------------------------------------------------------
__global__ void __launch_bounds__(256) attn_kernel(
    const float* __restrict__ out_note,
    const float* __restrict__ bias_note,
    const float* __restrict__ proj_note)
{
    extern __shared__ float As[];
    __shared__ float wred[8][32];
    const int tid = threadIdx.x;
    const int n = blockIdx.x;

    const float* src = out_note + (size_t)n * BATCH * 512;
    for (int i = tid; i < (BATCH * 512) / 4; i += 256)
        ((float4*)As)[i] = ((const float4*)src)[i];

    float attnacc[32];
#pragma unroll
    for (int bb = 0; bb < 32; bb++) attnacc[bb] = 0.0f;
    __syncthreads();

    for (int ee = 0; ee < 2; ee++) {
        const int e = ee * 256 + tid;
        float acc[32];
#pragma unroll
        for (int bb = 0; bb < 32; bb++) acc[bb] = 0.0f;
        for (int d4 = 0; d4 < 128; d4++) {
            const float4 wv = g_WAp[d4 * 512 + e];
#pragma unroll
            for (int bb = 0; bb < 32; bb++) {
                const float4 a = *(const float4*)&As[bb * 512 + d4 * 4];
                acc[bb] += wv.x * a.x + wv.y * a.y + wv.z * a.z + wv.w * a.w;
            }
        }
        const float be = bias_note[e], pe = proj_note[e];
#pragma unroll
        for (int bb = 0; bb < 32; bb++)
            attnacc[bb] += tanhf(acc[bb] + be) * pe;
    }
#pragma unroll
    for (int off = 16; off; off >>= 1)
#pragma unroll
        for (int bb = 0; bb < 32; bb++)
            attnacc[bb] += __shfl_xor_sync(0xffffffffu, attnacc[bb], off);
    const int wid = tid >> 5, lane = tid & 31;
    if (lane == 0)
#pragma unroll
        for (int bb = 0; bb < 32; bb++) wred[wid][bb] = attnacc[bb];
    __syncthreads();
    if (tid < 32) {
        float s = 0.0f;
#pragma unroll
        for (int w = 0; w < 8; w++) s += wred[w][tid];
        g_attn[n * BATCH + tid] = s;
    }
}

// ---------------------------------------------------------------------------
// Kernel 5: softmax + weighted sum + final linear. CTA per b.
// ---------------------------------------------------------------------------
__global__ void __launch_bounds__(256) final_kernel(
    const float* __restrict__ out_note,
    const float* __restrict__ lin_w,
    const float* __restrict__ lin_b,
    float* __restrict__ out)
{
    __shared__ float sa[64];
    __shared__ float vec[512];
    __shared__ float stats[2];
    const int tid = threadIdx.x;
    const int b = blockIdx.x;

    if (tid < 64) sa[tid] = g_attn[tid * BATCH + b];
    __syncthreads();
    if (tid < 32) {
        const float v0 = sa[tid], v1 = sa[tid + 32];
        float m = fmaxf(v0, v1);
#pragma unroll
        for (int o = 16; o; o >>= 1) m = fmaxf(m, __shfl_xor_sync(0xffffffffu, m, o));
        float s = expf(v0 - m) + expf(v1 - m);
#pragma unroll
        for (int o = 16; o; o >>= 1) s += __shfl_xor_sync(0xffffffffu, s, o);
        if (tid == 0) { stats[0] = m; stats[1] = s; }
    }
    __syncthreads();
    if (tid < 64) {
        const float nv = expf(sa[tid] - stats[0]) / stats[1];
        sa[tid] = nv;
        out[OFF_NORM + b * 64 + tid] = nv;
    }
    __syncthreads();
#pragma unroll
    for (int dd = 0; dd < 2; dd++) {
        const int d = dd * 256 + tid;
        float acc = 0.0f;
#pragma unroll 8
        for (int n = 0; n < 64; n++)
            acc += sa[n] * out_note[(size_t)(n * BATCH + b) * 512 + d];
        vec[d] = acc;
        out[OFF_VEC + b * 512 + d] = acc;
    }
    __syncthreads();
    if (tid < 64) {
        const int c = tid >> 5, lane = tid & 31;
        float p = 0.0f;
#pragma unroll 4
        for (int i = lane; i < 512; i += 32) p += lin_w[c * 512 + i] * vec[i];
#pragma unroll
        for (int o = 16; o; o >>= 1) p += __shfl_xor_sync(0xffffffffu, p, o);
        if (lane == 0) out[OFF_FIN + b * 2 + c] = p + lin_b[c];
    }
}

// ---------------------------------------------------------------------------
// Launcher — gru is the 4th launch (the profiler captures launch #4)
// ---------------------------------------------------------------------------
extern "C" void kernel_launch(void* const* d_in, const int* in_sizes, int n_in,
                              void* d_out, int out_size)
{
    (void)in_sizes; (void)n_in; (void)out_size;
    const int*   mini_batch = (const int*)d_in[0];
    const float* hidden     = (const float*)d_in[1];
    const float* embed      = (const float*)d_in[2];
    const float* conv_w     = (const float*)d_in[3];
    const float* conv_b     = (const float*)d_in[4];
    const float* w_ih_f     = (const float*)d_in[5];
    const float* w_hh_f     = (const float*)d_in[6];
    const float* b_ih_f     = (const float*)d_in[7];
    const float* b_hh_f     = (const float*)d_in[8];
    const float* w_ih_b     = (const float*)d_in[9];
    const float* w_hh_b     = (const float*)d_in[10];
    const float* b_ih_b     = (const float*)d_in[11];
    const float* b_hh_b     = (const float*)d_in[12];
    const float* W_note     = (const float*)d_in[13];
    const float* bias_note  = (const float*)d_in[14];
    const float* proj_note  = (const float*)d_in[15];
    const float* lin_w      = (const float*)d_in[16];
    const float* lin_b      = (const float*)d_in[17];
    float* out = (float*)d_out;

    cudaFuncSetAttribute(conv_mma_kernel,
                         cudaFuncAttributeMaxDynamicSharedMemorySize, CONV_SMEM);
    cudaFuncSetAttribute(attn_kernel,
                         cudaFuncAttributeMaxDynamicSharedMemorySize, 65536);

    prep_kernel<<<2048, 256>>>(conv_w, w_hh_f, w_hh_b, w_ih_f, w_ih_b, W_note);
    conv_mma_kernel<<<N_NOTES * BATCH * 4, 256, CONV_SMEM>>>(mini_batch, embed, conv_w);
    gi_kernel<<<128, 256>>>(b_ih_f, b_ih_b, conv_b);
    gru_kernel<<<64, 256>>>(b_hh_f, b_hh_b, hidden, out);
    attn_kernel<<<64, 256, 65536>>>(out, bias_note, proj_note);
    final_kernel<<<32, 256>>>(out, lin_w, lin_b, out);
}

// round 12
// speedup vs baseline: 1.8743x; 1.2892x over previous
#include <cuda_runtime.h>
#include <cuda_fp16.h>
#include <math.h>

// ---------------------------------------------------------------------------
// Problem constants
// ---------------------------------------------------------------------------
#define N_NOTES   64
#define N_WORDS   256
#define BATCH     32
#define WDIM      128
#define OC        256
#define HID       256

// Output layout (float32)
#define OFF_NORM 1048576
#define OFF_VEC  1050624
#define OFF_FIN  1067008

// ---------------------------------------------------------------------------
// Scratch (device globals)
// ---------------------------------------------------------------------------
__device__ unsigned int g_featmax[N_NOTES * BATCH * OC];
__device__ float        g_gi[2 * N_NOTES * BATCH * 3 * HID];
__device__ float        g_attn[N_NOTES * BATCH];
// conv W repacked per term/n-half: [term][nhalf][k=384][col=136 halfs]
__device__ __half       g_Bp[2][2][384][136];
// GRU weights, coalesced: [dir][(gate*64+k4)*256 + n] = float4 over k
__device__ float4       g_Wth[2 * 49152];   // w_hh
__device__ float4       g_Wti[2 * 49152];   // w_ih
// W_note coalesced: [d4*512 + e] = float4 over d
__device__ float4       g_WAp[65536];

// ---------------------------------------------------------------------------
// PTX helpers (mma.sync path — tcgen05 NOT supported by this ptxas target)
// ---------------------------------------------------------------------------
__device__ __forceinline__ void ldm_x4(unsigned* r, unsigned addr) {
    asm volatile("ldmatrix.sync.aligned.m8n8.x4.shared.b16 {%0,%1,%2,%3},[%4];"
        : "=r"(r[0]), "=r"(r[1]), "=r"(r[2]), "=r"(r[3]) : "r"(addr));
}
__device__ __forceinline__ void ldm_x4t(unsigned* r, unsigned addr) {
    asm volatile("ldmatrix.sync.aligned.m8n8.x4.trans.shared.b16 {%0,%1,%2,%3},[%4];"
        : "=r"(r[0]), "=r"(r[1]), "=r"(r[2]), "=r"(r[3]) : "r"(addr));
}
__device__ __forceinline__ void mma16816(float* c, const unsigned* a, const unsigned* b) {
    asm volatile("mma.sync.aligned.m16n8k16.row.col.f32.f16.f16.f32 "
        "{%0,%1,%2,%3},{%4,%5,%6,%7},{%8,%9},{%0,%1,%2,%3};"
        : "+f"(c[0]), "+f"(c[1]), "+f"(c[2]), "+f"(c[3])
        : "r"(a[0]), "r"(a[1]), "r"(a[2]), "r"(a[3]), "r"(b[0]), "r"(b[1]));
}
__device__ __forceinline__ void cp16(unsigned dst, const void* src) {
    asm volatile("cp.async.cg.shared.global [%0],[%1],16;" :: "r"(dst), "l"(src));
}
__device__ __forceinline__ void cp_commit() { asm volatile("cp.async.commit_group;"); }
template<int N> __device__ __forceinline__ void cp_wait() {
    asm volatile("cp.async.wait_group %0;" :: "n"(N));
}
__device__ __forceinline__ unsigned enc_key(float m) {
    unsigned bits = __float_as_uint(m);
    return (bits & 0x80000000u) ? ~bits : (bits | 0x80000000u);
}

// ---------------------------------------------------------------------------
// Kernel 0: fused prep — featmax init, conv-W split, w_hh/w_ih/W_note repack.
// ---------------------------------------------------------------------------
__global__ void __launch_bounds__(256) prep_kernel(
    const float* __restrict__ conv_w,
    const float* __restrict__ w_hh_f, const float* __restrict__ w_hh_b,
    const float* __restrict__ w_ih_f, const float* __restrict__ w_ih_b,
    const float* __restrict__ W_note)
{
    const int blk = blockIdx.x, tid = threadIdx.x;
    g_featmax[blk * 256 + tid] = 0u;

    if (blk < 384) {
        const int k = blk, n = tid;
        const float v = conv_w[n * 384 + k];
        const __half hi = __float2half(v);
        g_Bp[0][n >> 7][k][n & 127] = hi;
        g_Bp[1][n >> 7][k][n & 127] = __float2half(__half2float(hi) * 0.00390625f);
    } else if (blk < 1152) {
        const int idx = (blk - 384) * 256 + tid;
        const int which = idx / 98304;
        const int r = idx % 98304;
        const int n = r & 255, k4 = (r >> 8) & 63, gd = r >> 14;
        const int dir = gd / 3, gate = gd % 3;
        const float* W = which ? (dir ? w_ih_b : w_ih_f)
                               : (dir ? w_hh_b : w_hh_f);
        const float* src = W + (gate * 256 + n) * 256 + k4 * 4;
        const float4 v = make_float4(src[0], src[1], src[2], src[3]);
        float4* dst = which ? g_Wti : g_Wth;
        dst[dir * 49152 + (gate * 64 + k4) * 256 + n] = v;
    } else if (blk < 1408) {
        const int idx = (blk - 1152) * 256 + tid;
        const int e = idx & 511, d4 = idx >> 9;
        g_WAp[d4 * 512 + e] = make_float4(
            W_note[(d4 * 4 + 0) * 512 + e], W_note[(d4 * 4 + 1) * 512 + e],
            W_note[(d4 * 4 + 2) * 512 + e], W_note[(d4 * 4 + 3) * 512 + e]);
    }
}

// ---------------------------------------------------------------------------
// Kernel 1: conv as 2-term fp16 HMMA GEMM; CTA = (sample, l-half, n-half).
// (unchanged: measured 905 us, tensor 37.4%)
// ---------------------------------------------------------------------------
#define ES      136
#define EROWS   132
#define BSH     136
#define BCH     8704
#define EHI_OFF 0
#define ELO_OFF 35904
#define BHI_OFF 71808
#define BLO_OFF 89216
#define WMAX_OFF 106624
#define TOK_OFF  108672
#define CONV_SMEM 109312

__global__ void __launch_bounds__(256, 2) conv_mma_kernel(
    const int*   __restrict__ mini_batch,
    const float* __restrict__ embed,
    const float* __restrict__ conv_w)
{
    extern __shared__ char sm[];
    const unsigned smu = (unsigned)__cvta_generic_to_shared(sm);
    const int tid = threadIdx.x, lane = tid & 31, w = tid >> 5;
    const int mg = w >> 1;
    const int ng = w & 1;
    const int sample = blockIdx.x >> 2;
    const int half   = (blockIdx.x >> 1) & 1;
    const int nh     = blockIdx.x & 1;
    const int l0     = half << 7;
    const int n = sample >> 5, b = sample & 31;

    int* tok = (int*)(sm + TOK_OFF);
    const char* srcH = (const char*)&g_Bp[0][nh][0][0];
    const char* srcL = (const char*)&g_Bp[1][nh][0][0];

    for (int i = tid; i < BCH / 16; i += 256) {
        cp16(smu + BHI_OFF + i * 16, srcH + i * 16);
        cp16(smu + BLO_OFF + i * 16, srcL + i * 16);
    }
    cp_commit();
    for (int i = tid; i < BCH / 16; i += 256) {
        cp16(smu + BHI_OFF + BCH + i * 16, srcH + BCH + i * 16);
        cp16(smu + BLO_OFF + BCH + i * 16, srcL + BCH + i * 16);
    }
    cp_commit();

    if (tid < EROWS) {
        const int word = l0 + tid - 2;
        tok[tid] = (word >= 0 && word < N_WORDS)
                 ? mini_batch[(n * N_WORDS + word) * BATCH + b] : -1;
    }
    __syncthreads();

    for (int i = tid; i < EROWS * 32; i += 256) {
        const int row = i >> 5, q = i & 31;
        const int t = tok[row];
        float4 v;
        if (t >= 0) v = *(const float4*)(embed + (size_t)t * WDIM + q * 4);
        else        v = make_float4(0.f, 0.f, 0.f, 0.f);
        const __half h0 = __float2half(v.x), h1 = __float2half(v.y);
        const __half h2 = __float2half(v.z), h3 = __float2half(v.w);
        __half2 hp0 = __halves2half2(h0, h1);
        __half2 hp1 = __halves2half2(h2, h3);
        __half2 lp0 = __halves2half2(
            __float2half((v.x - __half2float(h0)) * 256.0f),
            __float2half((v.y - __half2float(h1)) * 256.0f));
        __half2 lp1 = __halves2half2(
            __float2half((v.z - __half2float(h2)) * 256.0f),
            __float2half((v.w - __half2float(h3)) * 256.0f));
        const unsigned off = (unsigned)(row * ES + q * 4) * 2;
        *(uint2*)(sm + EHI_OFF + off) = make_uint2(*(unsigned*)&hp0, *(unsigned*)&hp1);
        *(uint2*)(sm + ELO_OFF + off) = make_uint2(*(unsigned*)&lp0, *(unsigned*)&lp1);
    }

    float cm[2][8][4];
#pragma unroll
    for (int i = 0; i < 2; i++)
#pragma unroll
        for (int j = 0; j < 8; j++)
#pragma unroll
            for (int r = 0; r < 4; r++) cm[i][j][r] = 0.0f;
    __syncthreads();

    for (int c = 0; c < 12; c++) {
        const int stage = c & 1;
        if (c < 11) cp_wait<1>(); else cp_wait<0>();
        __syncthreads();

#pragma unroll
        for (int h = 0; h < 2; h++) {
            const int k0 = c * 32 + h * 16;
            const int seg = k0 >> 7, kk = k0 & 127;
            const unsigned acol = kk + ((lane >> 4) << 3);
            unsigned ahi[2][4], alo[2][4];
#pragma unroll
            for (int mt = 0; mt < 2; mt++) {
                const unsigned aoff =
                    ((mg * 32 + mt * 16 + (lane & 15) + seg) * ES + acol) * 2;
                ldm_x4(ahi[mt], smu + EHI_OFF + aoff);
                ldm_x4(alo[mt], smu + ELO_OFF + aoff);
            }
            const unsigned brow = (h << 4) + (lane & 15);
#pragma unroll
            for (int nn = 0; nn < 4; nn++) {
                const unsigned bcol = ng * 64 + nn * 16 + ((lane >> 4) << 3);
                const unsigned boff = stage * BCH + brow * (BSH * 2) + bcol * 2;
                unsigned bh[4], bl[4];
                ldm_x4t(bh, smu + BHI_OFF + boff);
                ldm_x4t(bl, smu + BLO_OFF + boff);
#pragma unroll
                for (int mt = 0; mt < 2; mt++) {
                    mma16816(cm[mt][nn * 2],     ahi[mt], bh);
                    mma16816(cm[mt][nn * 2 + 1], ahi[mt], bh + 2);
                    mma16816(cm[mt][nn * 2],     alo[mt], bl);
                    mma16816(cm[mt][nn * 2 + 1], alo[mt], bl + 2);
                }
            }
        }
        __syncthreads();
        if (c + 2 < 12) {
            const int coff = (c + 2) * BCH;
            for (int i = tid; i < BCH / 16; i += 256) {
                cp16(smu + BHI_OFF + stage * BCH + i * 16, srcH + coff + i * 16);
                cp16(smu + BLO_OFF + stage * BCH + i * 16, srcL + coff + i * 16);
            }
            cp_commit();
        }
    }

    float* wmax = (float*)(sm + WMAX_OFF);
#pragma unroll
    for (int t = 0; t < 8; t++) {
        float m0 = fmaxf(fmaxf(cm[0][t][0], cm[0][t][2]),
                         fmaxf(cm[1][t][0], cm[1][t][2]));
        float m1 = fmaxf(fmaxf(cm[0][t][1], cm[0][t][3]),
                         fmaxf(cm[1][t][1], cm[1][t][3]));
#pragma unroll
        for (int off = 4; off < 32; off <<= 1) {
            m0 = fmaxf(m0, __shfl_xor_sync(0xffffffffu, m0, off));
            m1 = fmaxf(m1, __shfl_xor_sync(0xffffffffu, m1, off));
        }
        if (lane < 4) {
            const int col = ng * 64 + (t >> 1) * 16 + (t & 1) * 8 + lane * 2;
            wmax[mg * 128 + col]     = m0;
            wmax[mg * 128 + col + 1] = m1;
        }
    }
    __syncthreads();
    if (tid < 128) {
        const float m = fmaxf(fmaxf(wmax[tid], wmax[128 + tid]),
                              fmaxf(wmax[256 + tid], wmax[384 + tid]));
        atomicMax(&g_featmax[sample * 256 + nh * 128 + tid], enc_key(m));
    }

    if (half == 1) {
        const int l_idx = tid >> 7;
        const int oc = nh * 128 + (tid & 127);
        const __half* e254 = (const __half*)(sm + EHI_OFF) + 128 * ES;
        const __half* e255 = (const __half*)(sm + EHI_OFF) + 129 * ES;
        const float* W = conv_w + oc * 384;
        float acc = 0.0f;
        if (l_idx == 0) {
#pragma unroll 8
            for (int d = 0; d < 128; d += 2) {
                const float2 w0 = *(const float2*)(W + d);
                const float2 w1 = *(const float2*)(W + 128 + d);
                const float2 ea = __half22float2(*(const __half2*)(e254 + d));
                const float2 eb = __half22float2(*(const __half2*)(e255 + d));
                acc += w0.x * ea.x + w0.y * ea.y + w1.x * eb.x + w1.y * eb.y;
            }
        } else {
#pragma unroll 8
            for (int d = 0; d < 128; d += 2) {
                const float2 w0 = *(const float2*)(W + d);
                const float2 eb = __half22float2(*(const __half2*)(e255 + d));
                acc += w0.x * eb.x + w0.y * eb.y;
            }
        }
        atomicMax(&g_featmax[sample * 256 + oc], enc_key(acc));
    }
}

// ---------------------------------------------------------------------------
// Kernel 2: gi = feat @ w_ih^T + b_ih — coalesced weights (g_Wti)
// ---------------------------------------------------------------------------
__global__ void __launch_bounds__(256) gi_kernel(
    const float* __restrict__ b_ih_f, const float* __restrict__ b_ih_b,
    const float* __restrict__ conv_b)
{
    __shared__ float As[BATCH * OC];
    const int tid = threadIdx.x;
    const int dir = blockIdx.x >> 6;
    const int n   = blockIdx.x & 63;

    for (int i = tid; i < BATCH * OC; i += 256) {
        const unsigned key = g_featmax[(n * BATCH + (i >> 8)) * 256 + (i & 255)];
        const unsigned bits = (key & 0x80000000u) ? (key & 0x7fffffffu) : ~key;
        As[i] = tanhf(conv_b[i & 255] + __uint_as_float(bits));
    }

    const float* bi = dir ? b_ih_b : b_ih_f;
    const float4* W0 = g_Wti + dir * 49152 + tid;
    const float4* W1 = W0 + 64 * 256;
    const float4* W2 = W0 + 128 * 256;

    float acc0[32], acc1[32], acc2[32];
#pragma unroll
    for (int bb = 0; bb < 32; bb++) { acc0[bb] = 0.f; acc1[bb] = 0.f; acc2[bb] = 0.f; }
    __syncthreads();

    for (int k4 = 0; k4 < OC / 4; k4++) {
        const float4 v0 = W0[k4 * 256];
        const float4 v1 = W1[k4 * 256];
        const float4 v2 = W2[k4 * 256];
#pragma unroll
        for (int bb = 0; bb < 32; bb++) {
            const float4 a = *(const float4*)&As[bb * OC + k4 * 4];
            acc0[bb] += v0.x * a.x + v0.y * a.y + v0.z * a.z + v0.w * a.w;
            acc1[bb] += v1.x * a.x + v1.y * a.y + v1.z * a.z + v1.w * a.w;
            acc2[bb] += v2.x * a.x + v2.y * a.y + v2.z * a.z + v2.w * a.w;
        }
    }
    const float bi0 = bi[tid], bi1 = bi[tid + 256], bi2 = bi[tid + 512];
    float* go = g_gi + (size_t)((dir * N_NOTES + n) * BATCH) * 768;
#pragma unroll 4
    for (int bb = 0; bb < 32; bb++) {
        go[bb * 768 +       tid] = acc0[bb] + bi0;
        go[bb * 768 + 256 + tid] = acc1[bb] + bi1;
        go[bb * 768 + 512 + tid] = acc2[bb] + bi2;
    }
}

// ---------------------------------------------------------------------------
// Kernel 3: GRU recurrence — CTA = (dir, batch-pair), 1024 threads.
// thread = (n = tid&255, ks = tid>>8): 64-long partial dot per gate, per 2 b.
// Partials reduced via smem; 512 threads do gate math.
// ---------------------------------------------------------------------------
__global__ void __launch_bounds__(1024, 1) gru_kernel(
    const float* __restrict__ b_hh_f, const float* __restrict__ b_hh_b,
    const float* __restrict__ hidden_state,
    float* __restrict__ out)
{
    __shared__ float h2[2][HID];
    __shared__ float red[4][3][2][HID];     // [ks][gate][bb][n] = 24 KB
    const int tid = threadIdx.x;
    const int dir = blockIdx.x >> 4;
    const int bp  = blockIdx.x & 15;
    const int b0  = bp * 2;
    const int i   = tid & 255;
    const int ks  = tid >> 8;

    const float* bhh = dir ? b_hh_b : b_hh_f;
    const float4* Wb = g_Wth + dir * 49152 + i;   // + (gate*64 + k4)*256

    float bh0 = 0.f, bh1 = 0.f, bh2 = 0.f;
    if (tid < 512) {
        const int bb = tid >> 8;
        h2[bb][i] = hidden_state[(dir * BATCH + b0 + bb) * HID + i];
        bh0 = bhh[i]; bh1 = bhh[i + 256]; bh2 = bhh[i + 512];
    }
    __syncthreads();

    for (int s = 0; s < N_NOTES; s++) {
        const int n = dir ? (N_NOTES - 1 - s) : s;
        float a0 = 0.f, a1 = 0.f, a2 = 0.f;   // partials for b0
        float c0 = 0.f, c1 = 0.f, c2 = 0.f;   // partials for b1
#pragma unroll 4
        for (int j = 0; j < 16; j++) {
            const int k4 = ks * 16 + j;
            const float4 w0 = Wb[(k4      ) * 256];
            const float4 w1 = Wb[(k4 +  64) * 256];
            const float4 w2 = Wb[(k4 + 128) * 256];
            const float4 hA = *(const float4*)&h2[0][k4 * 4];
            const float4 hB = *(const float4*)&h2[1][k4 * 4];
            a0 += w0.x * hA.x + w0.y * hA.y + w0.z * hA.z + w0.w * hA.w;
            c0 += w0.x * hB.x + w0.y * hB.y + w0.z * hB.z + w0.w * hB.w;
            a1 += w1.x * hA.x + w1.y * hA.y + w1.z * hA.z + w1.w * hA.w;
            c1 += w1.x * hB.x + w1.y * hB.y + w1.z * hB.z + w1.w * hB.w;
            a2 += w2.x * hA.x + w2.y * hA.y + w2.z * hA.z + w2.w * hA.w;
            c2 += w2.x * hB.x + w2.y * hB.y + w2.z * hB.z + w2.w * hB.w;
        }
        red[ks][0][0][i] = a0;  red[ks][0][1][i] = c0;
        red[ks][1][0][i] = a1;  red[ks][1][1][i] = c1;
        red[ks][2][0][i] = a2;  red[ks][2][1][i] = c2;
        __syncthreads();
        if (tid < 512) {
            const int bb = tid >> 8;
            const float g0 = bh0 + red[0][0][bb][i] + red[1][0][bb][i]
                                 + red[2][0][bb][i] + red[3][0][bb][i];
            const float g1 = bh1 + red[0][1][bb][i] + red[1][1][bb][i]
                                 + red[2][1][bb][i] + red[3][1][bb][i];
            const float g2 = bh2 + red[0][2][bb][i] + red[1][2][bb][i]
                                 + red[2][2][bb][i] + red[3][2][bb][i];
            const float* gp = g_gi + (size_t)((dir * N_NOTES + n) * BATCH + b0 + bb) * 768;
            const float r  = 1.0f / (1.0f + expf(-(gp[i]       + g0)));
            const float z  = 1.0f / (1.0f + expf(-(gp[i + 256] + g1)));
            const float nn = tanhf(gp[i + 512] + r * g2);
            const float hn = (1.0f - z) * nn + z * h2[bb][i];
            h2[bb][i] = hn;
            out[(size_t)(n * BATCH + b0 + bb) * 512 + dir * HID + i] = hn;
        }
        __syncthreads();
    }
}

// ---------------------------------------------------------------------------
// Kernel 4: additive attention scores — coalesced W_note (g_WAp)
// ---------------------------------------------------------------------------
__global__ void __launch_bounds__(256) attn_kernel(
    const float* __restrict__ out_note,
    const float* __restrict__ bias_note,
    const float* __restrict__ proj_note)
{
    extern __shared__ float As[];
    __shared__ float wred[8][32];
    const int tid = threadIdx.x;
    const int n = blockIdx.x;

    const float* src = out_note + (size_t)n * BATCH * 512;
    for (int i = tid; i < (BATCH * 512) / 4; i += 256)
        ((float4*)As)[i] = ((const float4*)src)[i];

    float attnacc[32];
#pragma unroll
    for (int bb = 0; bb < 32; bb++) attnacc[bb] = 0.0f;
    __syncthreads();

    for (int ee = 0; ee < 2; ee++) {
        const int e = ee * 256 + tid;
        float acc[32];
#pragma unroll
        for (int bb = 0; bb < 32; bb++) acc[bb] = 0.0f;
        for (int d4 = 0; d4 < 128; d4++) {
            const float4 wv = g_WAp[d4 * 512 + e];
#pragma unroll
            for (int bb = 0; bb < 32; bb++) {
                const float4 a = *(const float4*)&As[bb * 512 + d4 * 4];
                acc[bb] += wv.x * a.x + wv.y * a.y + wv.z * a.z + wv.w * a.w;
            }
        }
        const float be = bias_note[e], pe = proj_note[e];
#pragma unroll
        for (int bb = 0; bb < 32; bb++)
            attnacc[bb] += tanhf(acc[bb] + be) * pe;
    }
#pragma unroll
    for (int off = 16; off; off >>= 1)
#pragma unroll
        for (int bb = 0; bb < 32; bb++)
            attnacc[bb] += __shfl_xor_sync(0xffffffffu, attnacc[bb], off);
    const int wid = tid >> 5, lane = tid & 31;
    if (lane == 0)
#pragma unroll
        for (int bb = 0; bb < 32; bb++) wred[wid][bb] = attnacc[bb];
    __syncthreads();
    if (tid < 32) {
        float s = 0.0f;
#pragma unroll
        for (int w = 0; w < 8; w++) s += wred[w][tid];
        g_attn[n * BATCH + tid] = s;
    }
}

// ---------------------------------------------------------------------------
// Kernel 5: softmax + weighted sum + final linear. CTA per b.
// ---------------------------------------------------------------------------
__global__ void __launch_bounds__(256) final_kernel(
    const float* __restrict__ out_note,
    const float* __restrict__ lin_w,
    const float* __restrict__ lin_b,
    float* __restrict__ out)
{
    __shared__ float sa[64];
    __shared__ float vec[512];
    __shared__ float stats[2];
    const int tid = threadIdx.x;
    const int b = blockIdx.x;

    if (tid < 64) sa[tid] = g_attn[tid * BATCH + b];
    __syncthreads();
    if (tid < 32) {
        const float v0 = sa[tid], v1 = sa[tid + 32];
        float m = fmaxf(v0, v1);
#pragma unroll
        for (int o = 16; o; o >>= 1) m = fmaxf(m, __shfl_xor_sync(0xffffffffu, m, o));
        float s = expf(v0 - m) + expf(v1 - m);
#pragma unroll
        for (int o = 16; o; o >>= 1) s += __shfl_xor_sync(0xffffffffu, s, o);
        if (tid == 0) { stats[0] = m; stats[1] = s; }
    }
    __syncthreads();
    if (tid < 64) {
        const float nv = expf(sa[tid] - stats[0]) / stats[1];
        sa[tid] = nv;
        out[OFF_NORM + b * 64 + tid] = nv;
    }
    __syncthreads();
#pragma unroll
    for (int dd = 0; dd < 2; dd++) {
        const int d = dd * 256 + tid;
        float acc = 0.0f;
#pragma unroll 8
        for (int n = 0; n < 64; n++)
            acc += sa[n] * out_note[(size_t)(n * BATCH + b) * 512 + d];
        vec[d] = acc;
        out[OFF_VEC + b * 512 + d] = acc;
    }
    __syncthreads();
    if (tid < 64) {
        const int c = tid >> 5, lane = tid & 31;
        float p = 0.0f;
#pragma unroll 4
        for (int i = lane; i < 512; i += 32) p += lin_w[c * 512 + i] * vec[i];
#pragma unroll
        for (int o = 16; o; o >>= 1) p += __shfl_xor_sync(0xffffffffu, p, o);
        if (lane == 0) out[OFF_FIN + b * 2 + c] = p + lin_b[c];
    }
}

// ---------------------------------------------------------------------------
// Launcher — gru is the 4th launch (the profiler captures launch #4)
// ---------------------------------------------------------------------------
extern "C" void kernel_launch(void* const* d_in, const int* in_sizes, int n_in,
                              void* d_out, int out_size)
{
    (void)in_sizes; (void)n_in; (void)out_size;
    const int*   mini_batch = (const int*)d_in[0];
    const float* hidden     = (const float*)d_in[1];
    const float* embed      = (const float*)d_in[2];
    const float* conv_w     = (const float*)d_in[3];
    const float* conv_b     = (const float*)d_in[4];
    const float* w_ih_f     = (const float*)d_in[5];
    const float* w_hh_f     = (const float*)d_in[6];
    const float* b_ih_f     = (const float*)d_in[7];
    const float* b_hh_f     = (const float*)d_in[8];
    const float* w_ih_b     = (const float*)d_in[9];
    const float* w_hh_b     = (const float*)d_in[10];
    const float* b_ih_b     = (const float*)d_in[11];
    const float* b_hh_b     = (const float*)d_in[12];
    const float* W_note     = (const float*)d_in[13];
    const float* bias_note  = (const float*)d_in[14];
    const float* proj_note  = (const float*)d_in[15];
    const float* lin_w      = (const float*)d_in[16];
    const float* lin_b      = (const float*)d_in[17];
    float* out = (float*)d_out;

    cudaFuncSetAttribute(conv_mma_kernel,
                         cudaFuncAttributeMaxDynamicSharedMemorySize, CONV_SMEM);
    cudaFuncSetAttribute(attn_kernel,
                         cudaFuncAttributeMaxDynamicSharedMemorySize, 65536);

    prep_kernel<<<2048, 256>>>(conv_w, w_hh_f, w_hh_b, w_ih_f, w_ih_b, W_note);
    conv_mma_kernel<<<N_NOTES * BATCH * 4, 256, CONV_SMEM>>>(mini_batch, embed, conv_w);
    gi_kernel<<<128, 256>>>(b_ih_f, b_ih_b, conv_b);
    gru_kernel<<<32, 1024>>>(b_hh_f, b_hh_b, hidden, out);
    attn_kernel<<<64, 256, 65536>>>(out, bias_note, proj_note);
    final_kernel<<<32, 256>>>(out, lin_w, lin_b, out);
}

// round 13
// speedup vs baseline: 2.1182x; 1.1301x over previous
#include <cuda_runtime.h>
#include <cuda_fp16.h>
#include <math.h>

// ---------------------------------------------------------------------------
// Problem constants
// ---------------------------------------------------------------------------
#define N_NOTES   64
#define N_WORDS   256
#define BATCH     32
#define WDIM      128
#define OC        256
#define HID       256

// Output layout (float32)
#define OFF_NORM 1048576
#define OFF_VEC  1050624
#define OFF_FIN  1067008

// ---------------------------------------------------------------------------
// Scratch (device globals)
// ---------------------------------------------------------------------------
__device__ unsigned int g_featmax[N_NOTES * BATCH * OC];
__device__ float        g_gi[2 * N_NOTES * BATCH * 3 * HID];
__device__ float        g_attn[N_NOTES * BATCH];
// conv W repacked per term/n-half: [term][nhalf][k=384][col=136 halfs]
__device__ __half       g_Bp[2][2][384][136];
// GRU weights, coalesced: [dir][(gate*64+k4)*256 + n] = float4 over k
__device__ float4       g_Wth[2 * 49152];   // w_hh
__device__ float4       g_Wti[2 * 49152];   // w_ih
// W_note coalesced: [d4*512 + e] = float4 over d
__device__ float4       g_WAp[65536];

// ---------------------------------------------------------------------------
// PTX helpers
// ---------------------------------------------------------------------------
__device__ __forceinline__ void ldm_x4(unsigned* r, unsigned addr) {
    asm volatile("ldmatrix.sync.aligned.m8n8.x4.shared.b16 {%0,%1,%2,%3},[%4];"
        : "=r"(r[0]), "=r"(r[1]), "=r"(r[2]), "=r"(r[3]) : "r"(addr));
}
__device__ __forceinline__ void ldm_x4t(unsigned* r, unsigned addr) {
    asm volatile("ldmatrix.sync.aligned.m8n8.x4.trans.shared.b16 {%0,%1,%2,%3},[%4];"
        : "=r"(r[0]), "=r"(r[1]), "=r"(r[2]), "=r"(r[3]) : "r"(addr));
}
__device__ __forceinline__ void mma16816(float* c, const unsigned* a, const unsigned* b) {
    asm volatile("mma.sync.aligned.m16n8k16.row.col.f32.f16.f16.f32 "
        "{%0,%1,%2,%3},{%4,%5,%6,%7},{%8,%9},{%0,%1,%2,%3};"
        : "+f"(c[0]), "+f"(c[1]), "+f"(c[2]), "+f"(c[3])
        : "r"(a[0]), "r"(a[1]), "r"(a[2]), "r"(a[3]), "r"(b[0]), "r"(b[1]));
}
__device__ __forceinline__ void cp16(unsigned dst, const void* src) {
    asm volatile("cp.async.cg.shared.global [%0],[%1],16;" :: "r"(dst), "l"(src));
}
__device__ __forceinline__ void cp_commit() { asm volatile("cp.async.commit_group;"); }
template<int N> __device__ __forceinline__ void cp_wait() {
    asm volatile("cp.async.wait_group %0;" :: "n"(N));
}
__device__ __forceinline__ unsigned enc_key(float m) {
    unsigned bits = __float_as_uint(m);
    return (bits & 0x80000000u) ? ~bits : (bits | 0x80000000u);
}
__device__ __forceinline__ void dsmem_st(unsigned laddr, unsigned rank, float v) {
    unsigned ra;
    asm volatile("mapa.shared::cluster.u32 %0, %1, %2;" : "=r"(ra) : "r"(laddr), "r"(rank));
    asm volatile("st.shared::cluster.f32 [%0], %1;" :: "r"(ra), "f"(v) : "memory");
}
#define CLUSTER_BAR() do { \
    asm volatile("barrier.cluster.arrive.aligned;" ::: "memory"); \
    asm volatile("barrier.cluster.wait.aligned;" ::: "memory"); } while (0)

// ---------------------------------------------------------------------------
// Kernel 0: fused prep
// ---------------------------------------------------------------------------
__global__ void __launch_bounds__(256) prep_kernel(
    const float* __restrict__ conv_w,
    const float* __restrict__ w_hh_f, const float* __restrict__ w_hh_b,
    const float* __restrict__ w_ih_f, const float* __restrict__ w_ih_b,
    const float* __restrict__ W_note)
{
    const int blk = blockIdx.x, tid = threadIdx.x;
    g_featmax[blk * 256 + tid] = 0u;

    if (blk < 384) {
        const int k = blk, n = tid;
        const float v = conv_w[n * 384 + k];
        const __half hi = __float2half(v);
        g_Bp[0][n >> 7][k][n & 127] = hi;
        g_Bp[1][n >> 7][k][n & 127] = __float2half(__half2float(hi) * 0.00390625f);
    } else if (blk < 1152) {
        const int idx = (blk - 384) * 256 + tid;
        const int which = idx / 98304;
        const int r = idx % 98304;
        const int n = r & 255, k4 = (r >> 8) & 63, gd = r >> 14;
        const int dir = gd / 3, gate = gd % 3;
        const float* W = which ? (dir ? w_ih_b : w_ih_f)
                               : (dir ? w_hh_b : w_hh_f);
        const float* src = W + (gate * 256 + n) * 256 + k4 * 4;
        const float4 v = make_float4(src[0], src[1], src[2], src[3]);
        float4* dst = which ? g_Wti : g_Wth;
        dst[dir * 49152 + (gate * 64 + k4) * 256 + n] = v;
    } else if (blk < 1408) {
        const int idx = (blk - 1152) * 256 + tid;
        const int e = idx & 511, d4 = idx >> 9;
        g_WAp[d4 * 512 + e] = make_float4(
            W_note[(d4 * 4 + 0) * 512 + e], W_note[(d4 * 4 + 1) * 512 + e],
            W_note[(d4 * 4 + 2) * 512 + e], W_note[(d4 * 4 + 3) * 512 + e]);
    }
}

// ---------------------------------------------------------------------------
// Kernel 1: conv (unchanged: 905 us, tensor 37.4%)
// ---------------------------------------------------------------------------
#define ES      136
#define EROWS   132
#define BSH     136
#define BCH     8704
#define EHI_OFF 0
#define ELO_OFF 35904
#define BHI_OFF 71808
#define BLO_OFF 89216
#define WMAX_OFF 106624
#define TOK_OFF  108672
#define CONV_SMEM 109312

__global__ void __launch_bounds__(256, 2) conv_mma_kernel(
    const int*   __restrict__ mini_batch,
    const float* __restrict__ embed,
    const float* __restrict__ conv_w)
{
    extern __shared__ char sm[];
    const unsigned smu = (unsigned)__cvta_generic_to_shared(sm);
    const int tid = threadIdx.x, lane = tid & 31, w = tid >> 5;
    const int mg = w >> 1;
    const int ng = w & 1;
    const int sample = blockIdx.x >> 2;
    const int half   = (blockIdx.x >> 1) & 1;
    const int nh     = blockIdx.x & 1;
    const int l0     = half << 7;
    const int n = sample >> 5, b = sample & 31;

    int* tok = (int*)(sm + TOK_OFF);
    const char* srcH = (const char*)&g_Bp[0][nh][0][0];
    const char* srcL = (const char*)&g_Bp[1][nh][0][0];

    for (int i = tid; i < BCH / 16; i += 256) {
        cp16(smu + BHI_OFF + i * 16, srcH + i * 16);
        cp16(smu + BLO_OFF + i * 16, srcL + i * 16);
    }
    cp_commit();
    for (int i = tid; i < BCH / 16; i += 256) {
        cp16(smu + BHI_OFF + BCH + i * 16, srcH + BCH + i * 16);
        cp16(smu + BLO_OFF + BCH + i * 16, srcL + BCH + i * 16);
    }
    cp_commit();

    if (tid < EROWS) {
        const int word = l0 + tid - 2;
        tok[tid] = (word >= 0 && word < N_WORDS)
                 ? mini_batch[(n * N_WORDS + word) * BATCH + b] : -1;
    }
    __syncthreads();

    for (int i = tid; i < EROWS * 32; i += 256) {
        const int row = i >> 5, q = i & 31;
        const int t = tok[row];
        float4 v;
        if (t >= 0) v = *(const float4*)(embed + (size_t)t * WDIM + q * 4);
        else        v = make_float4(0.f, 0.f, 0.f, 0.f);
        const __half h0 = __float2half(v.x), h1 = __float2half(v.y);
        const __half h2 = __float2half(v.z), h3 = __float2half(v.w);
        __half2 hp0 = __halves2half2(h0, h1);
        __half2 hp1 = __halves2half2(h2, h3);
        __half2 lp0 = __halves2half2(
            __float2half((v.x - __half2float(h0)) * 256.0f),
            __float2half((v.y - __half2float(h1)) * 256.0f));
        __half2 lp1 = __halves2half2(
            __float2half((v.z - __half2float(h2)) * 256.0f),
            __float2half((v.w - __half2float(h3)) * 256.0f));
        const unsigned off = (unsigned)(row * ES + q * 4) * 2;
        *(uint2*)(sm + EHI_OFF + off) = make_uint2(*(unsigned*)&hp0, *(unsigned*)&hp1);
        *(uint2*)(sm + ELO_OFF + off) = make_uint2(*(unsigned*)&lp0, *(unsigned*)&lp1);
    }

    float cm[2][8][4];
#pragma unroll
    for (int i = 0; i < 2; i++)
#pragma unroll
        for (int j = 0; j < 8; j++)
#pragma unroll
            for (int r = 0; r < 4; r++) cm[i][j][r] = 0.0f;
    __syncthreads();

    for (int c = 0; c < 12; c++) {
        const int stage = c & 1;
        if (c < 11) cp_wait<1>(); else cp_wait<0>();
        __syncthreads();

#pragma unroll
        for (int h = 0; h < 2; h++) {
            const int k0 = c * 32 + h * 16;
            const int seg = k0 >> 7, kk = k0 & 127;
            const unsigned acol = kk + ((lane >> 4) << 3);
            unsigned ahi[2][4], alo[2][4];
#pragma unroll
            for (int mt = 0; mt < 2; mt++) {
                const unsigned aoff =
                    ((mg * 32 + mt * 16 + (lane & 15) + seg) * ES + acol) * 2;
                ldm_x4(ahi[mt], smu + EHI_OFF + aoff);
                ldm_x4(alo[mt], smu + ELO_OFF + aoff);
            }
            const unsigned brow = (h << 4) + (lane & 15);
#pragma unroll
            for (int nn = 0; nn < 4; nn++) {
                const unsigned bcol = ng * 64 + nn * 16 + ((lane >> 4) << 3);
                const unsigned boff = stage * BCH + brow * (BSH * 2) + bcol * 2;
                unsigned bh[4], bl[4];
                ldm_x4t(bh, smu + BHI_OFF + boff);
                ldm_x4t(bl, smu + BLO_OFF + boff);
#pragma unroll
                for (int mt = 0; mt < 2; mt++) {
                    mma16816(cm[mt][nn * 2],     ahi[mt], bh);
                    mma16816(cm[mt][nn * 2 + 1], ahi[mt], bh + 2);
                    mma16816(cm[mt][nn * 2],     alo[mt], bl);
                    mma16816(cm[mt][nn * 2 + 1], alo[mt], bl + 2);
                }
            }
        }
        __syncthreads();
        if (c + 2 < 12) {
            const int coff = (c + 2) * BCH;
            for (int i = tid; i < BCH / 16; i += 256) {
                cp16(smu + BHI_OFF + stage * BCH + i * 16, srcH + coff + i * 16);
                cp16(smu + BLO_OFF + stage * BCH + i * 16, srcL + coff + i * 16);
            }
            cp_commit();
        }
    }

    float* wmax = (float*)(sm + WMAX_OFF);
#pragma unroll
    for (int t = 0; t < 8; t++) {
        float m0 = fmaxf(fmaxf(cm[0][t][0], cm[0][t][2]),
                         fmaxf(cm[1][t][0], cm[1][t][2]));
        float m1 = fmaxf(fmaxf(cm[0][t][1], cm[0][t][3]),
                         fmaxf(cm[1][t][1], cm[1][t][3]));
#pragma unroll
        for (int off = 4; off < 32; off <<= 1) {
            m0 = fmaxf(m0, __shfl_xor_sync(0xffffffffu, m0, off));
            m1 = fmaxf(m1, __shfl_xor_sync(0xffffffffu, m1, off));
        }
        if (lane < 4) {
            const int col = ng * 64 + (t >> 1) * 16 + (t & 1) * 8 + lane * 2;
            wmax[mg * 128 + col]     = m0;
            wmax[mg * 128 + col + 1] = m1;
        }
    }
    __syncthreads();
    if (tid < 128) {
        const float m = fmaxf(fmaxf(wmax[tid], wmax[128 + tid]),
                              fmaxf(wmax[256 + tid], wmax[384 + tid]));
        atomicMax(&g_featmax[sample * 256 + nh * 128 + tid], enc_key(m));
    }

    if (half == 1) {
        const int l_idx = tid >> 7;
        const int oc = nh * 128 + (tid & 127);
        const __half* e254 = (const __half*)(sm + EHI_OFF) + 128 * ES;
        const __half* e255 = (const __half*)(sm + EHI_OFF) + 129 * ES;
        const float* W = conv_w + oc * 384;
        float acc = 0.0f;
        if (l_idx == 0) {
#pragma unroll 8
            for (int d = 0; d < 128; d += 2) {
                const float2 w0 = *(const float2*)(W + d);
                const float2 w1 = *(const float2*)(W + 128 + d);
                const float2 ea = __half22float2(*(const __half2*)(e254 + d));
                const float2 eb = __half22float2(*(const __half2*)(e255 + d));
                acc += w0.x * ea.x + w0.y * ea.y + w1.x * eb.x + w1.y * eb.y;
            }
        } else {
#pragma unroll 8
            for (int d = 0; d < 128; d += 2) {
                const float2 w0 = *(const float2*)(W + d);
                const float2 eb = __half22float2(*(const __half2*)(e255 + d));
                acc += w0.x * eb.x + w0.y * eb.y;
            }
        }
        atomicMax(&g_featmax[sample * 256 + oc], enc_key(acc));
    }
}

// ---------------------------------------------------------------------------
// Kernel 2: gi = feat @ w_ih^T + b_ih (coalesced g_Wti)
// ---------------------------------------------------------------------------
__global__ void __launch_bounds__(256) gi_kernel(
    const float* __restrict__ b_ih_f, const float* __restrict__ b_ih_b,
    const float* __restrict__ conv_b)
{
    __shared__ float As[BATCH * OC];
    const int tid = threadIdx.x;
    const int dir = blockIdx.x >> 6;
    const int n   = blockIdx.x & 63;

    for (int i = tid; i < BATCH * OC; i += 256) {
        const unsigned key = g_featmax[(n * BATCH + (i >> 8)) * 256 + (i & 255)];
        const unsigned bits = (key & 0x80000000u) ? (key & 0x7fffffffu) : ~key;
        As[i] = tanhf(conv_b[i & 255] + __uint_as_float(bits));
    }

    const float* bi = dir ? b_ih_b : b_ih_f;
    const float4* W0 = g_Wti + dir * 49152 + tid;
    const float4* W1 = W0 + 64 * 256;
    const float4* W2 = W0 + 128 * 256;

    float acc0[32], acc1[32], acc2[32];
#pragma unroll
    for (int bb = 0; bb < 32; bb++) { acc0[bb] = 0.f; acc1[bb] = 0.f; acc2[bb] = 0.f; }
    __syncthreads();

    for (int k4 = 0; k4 < OC / 4; k4++) {
        const float4 v0 = W0[k4 * 256];
        const float4 v1 = W1[k4 * 256];
        const float4 v2 = W2[k4 * 256];
#pragma unroll
        for (int bb = 0; bb < 32; bb++) {
            const float4 a = *(const float4*)&As[bb * OC + k4 * 4];
            acc0[bb] += v0.x * a.x + v0.y * a.y + v0.z * a.z + v0.w * a.w;
            acc1[bb] += v1.x * a.x + v1.y * a.y + v1.z * a.z + v1.w * a.w;
            acc2[bb] += v2.x * a.x + v2.y * a.y + v2.z * a.z + v2.w * a.w;
        }
    }
    const float bi0 = bi[tid], bi1 = bi[tid + 256], bi2 = bi[tid + 512];
    float* go = g_gi + (size_t)((dir * N_NOTES + n) * BATCH) * 768;
#pragma unroll 4
    for (int bb = 0; bb < 32; bb++) {
        go[bb * 768 +       tid] = acc0[bb] + bi0;
        go[bb * 768 + 256 + tid] = acc1[bb] + bi1;
        go[bb * 768 + 512 + tid] = acc2[bb] + bi2;
    }
}

// ---------------------------------------------------------------------------
// Kernel 3: GRU — cluster of 4 CTAs = n-quarters of (dir, batch-pair).
// 128 CTAs x 1024 threads. Each CTA streams 196KB of weights per step;
// h exchanged via DSMEM with parity double-buffering + 1 cluster barrier.
// ---------------------------------------------------------------------------
__global__ void __launch_bounds__(1024, 1) __cluster_dims__(4, 1, 1)
gru_kernel(const float* __restrict__ b_hh_f, const float* __restrict__ b_hh_b,
           const float* __restrict__ hidden_state,
           float* __restrict__ out)
{
    __shared__ float h2[2][2][HID];          // [parity][bb][n]  4 KB
    __shared__ float red[16][3][2][64];      // [ks][gate][bb][i] 24 KB
    const int tid = threadIdx.x;
    const int nq   = blockIdx.x & 3;
    const int cidx = blockIdx.x >> 2;        // (dir, bp)
    const int dir  = cidx >> 4;
    const int bp   = cidx & 15;
    const int b0   = bp * 2;
    const int i    = tid & 63;
    const int ks   = tid >> 6;               // 0..15
    const int ig   = nq * 64 + i;            // global n

    const float* bhh = dir ? b_hh_b : b_hh_f;
    const float4* Wb = g_Wth + dir * 49152 + ig;   // + (gate*64 + k4)*256

    if (tid < 512) {
        const int bb = tid >> 8, nn = tid & 255;
        h2[0][bb][nn] = hidden_state[(dir * BATCH + b0 + bb) * HID + nn];
    }
    float bh0 = 0.f, bh1 = 0.f, bh2 = 0.f;
    if (tid < 128) { bh0 = bhh[ig]; bh1 = bhh[ig + 256]; bh2 = bhh[ig + 512]; }
    __syncthreads();
    CLUSTER_BAR();

    for (int s = 0; s < N_NOTES; s++) {
        const int par = s & 1;
        const int n = dir ? (N_NOTES - 1 - s) : s;
        float a0 = 0.f, a1 = 0.f, a2 = 0.f;   // batch b0
        float c0 = 0.f, c1 = 0.f, c2 = 0.f;   // batch b0+1
#pragma unroll
        for (int j = 0; j < 4; j++) {
            const int k4 = ks * 4 + j;
            const float4 w0 = Wb[(k4      ) * 256];
            const float4 w1 = Wb[(k4 +  64) * 256];
            const float4 w2 = Wb[(k4 + 128) * 256];
            const float4 hA = *(const float4*)&h2[par][0][k4 * 4];
            const float4 hB = *(const float4*)&h2[par][1][k4 * 4];
            a0 += w0.x * hA.x + w0.y * hA.y + w0.z * hA.z + w0.w * hA.w;
            c0 += w0.x * hB.x + w0.y * hB.y + w0.z * hB.z + w0.w * hB.w;
            a1 += w1.x * hA.x + w1.y * hA.y + w1.z * hA.z + w1.w * hA.w;
            c1 += w1.x * hB.x + w1.y * hB.y + w1.z * hB.z + w1.w * hB.w;
            a2 += w2.x * hA.x + w2.y * hA.y + w2.z * hA.z + w2.w * hA.w;
            c2 += w2.x * hB.x + w2.y * hB.y + w2.z * hB.z + w2.w * hB.w;
        }
        red[ks][0][0][i] = a0;  red[ks][0][1][i] = c0;
        red[ks][1][0][i] = a1;  red[ks][1][1][i] = c1;
        red[ks][2][0][i] = a2;  red[ks][2][1][i] = c2;
        __syncthreads();
        if (tid < 128) {
            const int bb = tid >> 6;
            float g0 = bh0, g1 = bh1, g2 = bh2;
#pragma unroll
            for (int q = 0; q < 16; q++) {
                g0 += red[q][0][bb][i];
                g1 += red[q][1][bb][i];
                g2 += red[q][2][bb][i];
            }
            const float* gp = g_gi + (size_t)((dir * N_NOTES + n) * BATCH + b0 + bb) * 768;
            const float r  = 1.0f / (1.0f + expf(-(gp[ig]       + g0)));
            const float z  = 1.0f / (1.0f + expf(-(gp[ig + 256] + g1)));
            const float nn = tanhf(gp[ig + 512] + r * g2);
            const float hn = (1.0f - z) * nn + z * h2[par][bb][ig];
            const unsigned la = (unsigned)__cvta_generic_to_shared(&h2[par ^ 1][bb][ig]);
#pragma unroll
            for (unsigned rk = 0; rk < 4; rk++) dsmem_st(la, rk, hn);
            out[(size_t)(n * BATCH + b0 + bb) * 512 + dir * HID + ig] = hn;
        }
        CLUSTER_BAR();
    }
}

// ---------------------------------------------------------------------------
// Kernel 4: additive attention scores (coalesced g_WAp)
// ---------------------------------------------------------------------------
__global__ void __launch_bounds__(256) attn_kernel(
    const float* __restrict__ out_note,
    const float* __restrict__ bias_note,
    const float* __restrict__ proj_note)
{
    extern __shared__ float As[];
    __shared__ float wred[8][32];
    const int tid = threadIdx.x;
    const int n = blockIdx.x;

    const float* src = out_note + (size_t)n * BATCH * 512;
    for (int i = tid; i < (BATCH * 512) / 4; i += 256)
        ((float4*)As)[i] = ((const float4*)src)[i];

    float attnacc[32];
#pragma unroll
    for (int bb = 0; bb < 32; bb++) attnacc[bb] = 0.0f;
    __syncthreads();

    for (int ee = 0; ee < 2; ee++) {
        const int e = ee * 256 + tid;
        float acc[32];
#pragma unroll
        for (int bb = 0; bb < 32; bb++) acc[bb] = 0.0f;
        for (int d4 = 0; d4 < 128; d4++) {
            const float4 wv = g_WAp[d4 * 512 + e];
#pragma unroll
            for (int bb = 0; bb < 32; bb++) {
                const float4 a = *(const float4*)&As[bb * 512 + d4 * 4];
                acc[bb] += wv.x * a.x + wv.y * a.y + wv.z * a.z + wv.w * a.w;
            }
        }
        const float be = bias_note[e], pe = proj_note[e];
#pragma unroll
        for (int bb = 0; bb < 32; bb++)
            attnacc[bb] += tanhf(acc[bb] + be) * pe;
    }
#pragma unroll
    for (int off = 16; off; off >>= 1)
#pragma unroll
        for (int bb = 0; bb < 32; bb++)
            attnacc[bb] += __shfl_xor_sync(0xffffffffu, attnacc[bb], off);
    const int wid = tid >> 5, lane = tid & 31;
    if (lane == 0)
#pragma unroll
        for (int bb = 0; bb < 32; bb++) wred[wid][bb] = attnacc[bb];
    __syncthreads();
    if (tid < 32) {
        float s = 0.0f;
#pragma unroll
        for (int w = 0; w < 8; w++) s += wred[w][tid];
        g_attn[n * BATCH + tid] = s;
    }
}

// ---------------------------------------------------------------------------
// Kernel 5: softmax + weighted sum + final linear. CTA per b.
// ---------------------------------------------------------------------------
__global__ void __launch_bounds__(256) final_kernel(
    const float* __restrict__ out_note,
    const float* __restrict__ lin_w,
    const float* __restrict__ lin_b,
    float* __restrict__ out)
{
    __shared__ float sa[64];
    __shared__ float vec[512];
    __shared__ float stats[2];
    const int tid = threadIdx.x;
    const int b = blockIdx.x;

    if (tid < 64) sa[tid] = g_attn[tid * BATCH + b];
    __syncthreads();
    if (tid < 32) {
        const float v0 = sa[tid], v1 = sa[tid + 32];
        float m = fmaxf(v0, v1);
#pragma unroll
        for (int o = 16; o; o >>= 1) m = fmaxf(m, __shfl_xor_sync(0xffffffffu, m, o));
        float s = expf(v0 - m) + expf(v1 - m);
#pragma unroll
        for (int o = 16; o; o >>= 1) s += __shfl_xor_sync(0xffffffffu, s, o);
        if (tid == 0) { stats[0] = m; stats[1] = s; }
    }
    __syncthreads();
    if (tid < 64) {
        const float nv = expf(sa[tid] - stats[0]) / stats[1];
        sa[tid] = nv;
        out[OFF_NORM + b * 64 + tid] = nv;
    }
    __syncthreads();
#pragma unroll
    for (int dd = 0; dd < 2; dd++) {
        const int d = dd * 256 + tid;
        float acc = 0.0f;
#pragma unroll 8
        for (int n = 0; n < 64; n++)
            acc += sa[n] * out_note[(size_t)(n * BATCH + b) * 512 + d];
        vec[d] = acc;
        out[OFF_VEC + b * 512 + d] = acc;
    }
    __syncthreads();
    if (tid < 64) {
        const int c = tid >> 5, lane = tid & 31;
        float p = 0.0f;
#pragma unroll 4
        for (int i = lane; i < 512; i += 32) p += lin_w[c * 512 + i] * vec[i];
#pragma unroll
        for (int o = 16; o; o >>= 1) p += __shfl_xor_sync(0xffffffffu, p, o);
        if (lane == 0) out[OFF_FIN + b * 2 + c] = p + lin_b[c];
    }
}

// ---------------------------------------------------------------------------
// Launcher — gru is the 4th launch (profiler captures launch #4)
// ---------------------------------------------------------------------------
extern "C" void kernel_launch(void* const* d_in, const int* in_sizes, int n_in,
                              void* d_out, int out_size)
{
    (void)in_sizes; (void)n_in; (void)out_size;
    const int*   mini_batch = (const int*)d_in[0];
    const float* hidden     = (const float*)d_in[1];
    const float* embed      = (const float*)d_in[2];
    const float* conv_w     = (const float*)d_in[3];
    const float* conv_b     = (const float*)d_in[4];
    const float* w_ih_f     = (const float*)d_in[5];
    const float* w_hh_f     = (const float*)d_in[6];
    const float* b_ih_f     = (const float*)d_in[7];
    const float* b_hh_f     = (const float*)d_in[8];
    const float* w_ih_b     = (const float*)d_in[9];
    const float* w_hh_b     = (const float*)d_in[10];
    const float* b_ih_b     = (const float*)d_in[11];
    const float* b_hh_b     = (const float*)d_in[12];
    const float* W_note     = (const float*)d_in[13];
    const float* bias_note  = (const float*)d_in[14];
    const float* proj_note  = (const float*)d_in[15];
    const float* lin_w      = (const float*)d_in[16];
    const float* lin_b      = (const float*)d_in[17];
    float* out = (float*)d_out;

    cudaFuncSetAttribute(conv_mma_kernel,
                         cudaFuncAttributeMaxDynamicSharedMemorySize, CONV_SMEM);
    cudaFuncSetAttribute(attn_kernel,
                         cudaFuncAttributeMaxDynamicSharedMemorySize, 65536);

    prep_kernel<<<2048, 256>>>(conv_w, w_hh_f, w_hh_b, w_ih_f, w_ih_b, W_note);
    conv_mma_kernel<<<N_NOTES * BATCH * 4, 256, CONV_SMEM>>>(mini_batch, embed, conv_w);
    gi_kernel<<<128, 256>>>(b_ih_f, b_ih_b, conv_b);
    gru_kernel<<<128, 1024>>>(b_hh_f, b_hh_b, hidden, out);
    attn_kernel<<<64, 256, 65536>>>(out, bias_note, proj_note);
    final_kernel<<<32, 256>>>(out, lin_w, lin_b, out);
}

// round 14
// speedup vs baseline: 2.4839x; 1.1727x over previous
#include <cuda_runtime.h>
#include <cuda_fp16.h>
#include <math.h>

// ---------------------------------------------------------------------------
// Problem constants
// ---------------------------------------------------------------------------
#define N_NOTES   64
#define N_WORDS   256
#define BATCH     32
#define WDIM      128
#define OC        256
#define HID       256

// Output layout (float32)
#define OFF_NORM 1048576
#define OFF_VEC  1050624
#define OFF_FIN  1067008

// ---------------------------------------------------------------------------
// Scratch (device globals)
// ---------------------------------------------------------------------------
__device__ unsigned int g_featmax[N_NOTES * BATCH * OC];
__device__ float        g_gi[2 * N_NOTES * BATCH * 3 * HID];
__device__ float        g_attn[N_NOTES * BATCH];
// conv W fp16, repacked per n-half: [nhalf][k=384][col=136 halfs]
__device__ __half       g_Bp[2][384][136];
// GRU weights, coalesced: [dir][(gate*64+k4)*256 + n] = float4 over k
__device__ float4       g_Wth[2 * 49152];   // w_hh
__device__ float4       g_Wti[2 * 49152];   // w_ih
// W_note coalesced: [d4*512 + e] = float4 over d
__device__ float4       g_WAp[65536];

// ---------------------------------------------------------------------------
// PTX helpers
// ---------------------------------------------------------------------------
__device__ __forceinline__ void ldm_x4(unsigned* r, unsigned addr) {
    asm volatile("ldmatrix.sync.aligned.m8n8.x4.shared.b16 {%0,%1,%2,%3},[%4];"
        : "=r"(r[0]), "=r"(r[1]), "=r"(r[2]), "=r"(r[3]) : "r"(addr));
}
__device__ __forceinline__ void ldm_x4t(unsigned* r, unsigned addr) {
    asm volatile("ldmatrix.sync.aligned.m8n8.x4.trans.shared.b16 {%0,%1,%2,%3},[%4];"
        : "=r"(r[0]), "=r"(r[1]), "=r"(r[2]), "=r"(r[3]) : "r"(addr));
}
__device__ __forceinline__ void mma16816(float* c, const unsigned* a, const unsigned* b) {
    asm volatile("mma.sync.aligned.m16n8k16.row.col.f32.f16.f16.f32 "
        "{%0,%1,%2,%3},{%4,%5,%6,%7},{%8,%9},{%0,%1,%2,%3};"
        : "+f"(c[0]), "+f"(c[1]), "+f"(c[2]), "+f"(c[3])
        : "r"(a[0]), "r"(a[1]), "r"(a[2]), "r"(a[3]), "r"(b[0]), "r"(b[1]));
}
__device__ __forceinline__ void cp16(unsigned dst, const void* src) {
    asm volatile("cp.async.cg.shared.global [%0],[%1],16;" :: "r"(dst), "l"(src));
}
__device__ __forceinline__ void cp_commit() { asm volatile("cp.async.commit_group;"); }
template<int N> __device__ __forceinline__ void cp_wait() {
    asm volatile("cp.async.wait_group %0;" :: "n"(N));
}
__device__ __forceinline__ unsigned enc_key(float m) {
    unsigned bits = __float_as_uint(m);
    return (bits & 0x80000000u) ? ~bits : (bits | 0x80000000u);
}
__device__ __forceinline__ void dsmem_st(unsigned laddr, unsigned rank, float v) {
    unsigned ra;
    asm volatile("mapa.shared::cluster.u32 %0, %1, %2;" : "=r"(ra) : "r"(laddr), "r"(rank));
    asm volatile("st.shared::cluster.f32 [%0], %1;" :: "r"(ra), "f"(v) : "memory");
}
#define CLUSTER_BAR() do { \
    asm volatile("barrier.cluster.arrive.aligned;" ::: "memory"); \
    asm volatile("barrier.cluster.wait.aligned;" ::: "memory"); } while (0)

// ---------------------------------------------------------------------------
// Kernel 0a: featmax init + conv W fp16 repack
// ---------------------------------------------------------------------------
__global__ void __launch_bounds__(256) prep_a_kernel(const float* __restrict__ conv_w)
{
    const int blk = blockIdx.x, tid = threadIdx.x;
    g_featmax[blk * 256 + tid] = 0u;
    if (blk < 384) {
        const int k = blk, n = tid;
        g_Bp[n >> 7][k][n & 127] = __float2half(conv_w[n * 384 + k]);
    }
}

// ---------------------------------------------------------------------------
// Kernel 0b: GRU weight repack (w_hh, w_ih)
// ---------------------------------------------------------------------------
__global__ void __launch_bounds__(256) prep_b_kernel(
    const float* __restrict__ w_hh_f, const float* __restrict__ w_hh_b,
    const float* __restrict__ w_ih_f, const float* __restrict__ w_ih_b)
{
    const int idx = blockIdx.x * 256 + threadIdx.x;   // 0..196607
    const int which = idx / 98304;
    const int r = idx % 98304;
    const int n = r & 255, k4 = (r >> 8) & 63, gd = r >> 14;
    const int dir = gd / 3, gate = gd % 3;
    const float* W = which ? (dir ? w_ih_b : w_ih_f)
                           : (dir ? w_hh_b : w_hh_f);
    const float* src = W + (gate * 256 + n) * 256 + k4 * 4;
    const float4 v = make_float4(src[0], src[1], src[2], src[3]);
    float4* dst = which ? g_Wti : g_Wth;
    dst[dir * 49152 + (gate * 64 + k4) * 256 + n] = v;
}

// ---------------------------------------------------------------------------
// Kernel 0c: W_note repack
// ---------------------------------------------------------------------------
__global__ void __launch_bounds__(256) prep_c_kernel(const float* __restrict__ W_note)
{
    const int idx = blockIdx.x * 256 + threadIdx.x;   // 0..65535
    const int e = idx & 511, d4 = idx >> 9;
    g_WAp[d4 * 512 + e] = make_float4(
        W_note[(d4 * 4 + 0) * 512 + e], W_note[(d4 * 4 + 1) * 512 + e],
        W_note[(d4 * 4 + 2) * 512 + e], W_note[(d4 * 4 + 3) * 512 + e]);
}

// ---------------------------------------------------------------------------
// Kernel 1: conv — SINGLE-TERM fp16 HMMA; CTA = (sample, l-half, n-half).
// 256 threads, M=128 x N=128 per CTA, warp tile m32 x n64. 2 CTAs/SM.
// ---------------------------------------------------------------------------
#define ES      136
#define EROWS   132
#define BSH     136
#define BCH     8704
#define EHI_OFF 0
#define B_OFF   35904      // 2 stages x 8704
#define WMAX_OFF 53312     // 4 x 128 floats
#define TOK_OFF  55360     // 132 ints
#define CONV_SMEM 55936

__global__ void __launch_bounds__(256, 2) conv_mma_kernel(
    const int*   __restrict__ mini_batch,
    const float* __restrict__ embed,
    const float* __restrict__ conv_w)
{
    extern __shared__ char sm[];
    const unsigned smu = (unsigned)__cvta_generic_to_shared(sm);
    const int tid = threadIdx.x, lane = tid & 31, w = tid >> 5;
    const int mg = w >> 1;
    const int ng = w & 1;
    const int sample = blockIdx.x >> 2;
    const int half   = (blockIdx.x >> 1) & 1;
    const int nh     = blockIdx.x & 1;
    const int l0     = half << 7;
    const int n = sample >> 5, b = sample & 31;

    int* tok = (int*)(sm + TOK_OFF);
    const char* srcB = (const char*)&g_Bp[nh][0][0];

    for (int i = tid; i < BCH / 16; i += 256)
        cp16(smu + B_OFF + i * 16, srcB + i * 16);
    cp_commit();
    for (int i = tid; i < BCH / 16; i += 256)
        cp16(smu + B_OFF + BCH + i * 16, srcB + BCH + i * 16);
    cp_commit();

    if (tid < EROWS) {
        const int word = l0 + tid - 2;
        tok[tid] = (word >= 0 && word < N_WORDS)
                 ? mini_batch[(n * N_WORDS + word) * BATCH + b] : -1;
    }
    __syncthreads();

    // build E (fp16)
    for (int i = tid; i < EROWS * 32; i += 256) {
        const int row = i >> 5, q = i & 31;
        const int t = tok[row];
        float4 v;
        if (t >= 0) v = *(const float4*)(embed + (size_t)t * WDIM + q * 4);
        else        v = make_float4(0.f, 0.f, 0.f, 0.f);
        __half2 hp0 = __halves2half2(__float2half(v.x), __float2half(v.y));
        __half2 hp1 = __halves2half2(__float2half(v.z), __float2half(v.w));
        *(uint2*)(sm + EHI_OFF + (unsigned)(row * ES + q * 4) * 2) =
            make_uint2(*(unsigned*)&hp0, *(unsigned*)&hp1);
    }

    float cm[2][8][4];
#pragma unroll
    for (int i = 0; i < 2; i++)
#pragma unroll
        for (int j = 0; j < 8; j++)
#pragma unroll
            for (int r = 0; r < 4; r++) cm[i][j][r] = 0.0f;
    __syncthreads();

    for (int c = 0; c < 12; c++) {
        const int stage = c & 1;
        if (c < 11) cp_wait<1>(); else cp_wait<0>();
        __syncthreads();

#pragma unroll
        for (int h = 0; h < 2; h++) {
            const int k0 = c * 32 + h * 16;
            const int seg = k0 >> 7, kk = k0 & 127;
            const unsigned acol = kk + ((lane >> 4) << 3);
            unsigned ahi[2][4];
#pragma unroll
            for (int mt = 0; mt < 2; mt++) {
                const unsigned aoff =
                    ((mg * 32 + mt * 16 + (lane & 15) + seg) * ES + acol) * 2;
                ldm_x4(ahi[mt], smu + EHI_OFF + aoff);
            }
            const unsigned brow = (h << 4) + (lane & 15);
#pragma unroll
            for (int nn = 0; nn < 4; nn++) {
                const unsigned bcol = ng * 64 + nn * 16 + ((lane >> 4) << 3);
                unsigned bh[4];
                ldm_x4t(bh, smu + B_OFF + stage * BCH + brow * (BSH * 2) + bcol * 2);
#pragma unroll
                for (int mt = 0; mt < 2; mt++) {
                    mma16816(cm[mt][nn * 2],     ahi[mt], bh);
                    mma16816(cm[mt][nn * 2 + 1], ahi[mt], bh + 2);
                }
            }
        }
        __syncthreads();
        if (c + 2 < 12) {
            const int coff = (c + 2) * BCH;
            for (int i = tid; i < BCH / 16; i += 256)
                cp16(smu + B_OFF + stage * BCH + i * 16, srcB + coff + i * 16);
            cp_commit();
        }
    }

    float* wmax = (float*)(sm + WMAX_OFF);
#pragma unroll
    for (int t = 0; t < 8; t++) {
        float m0 = fmaxf(fmaxf(cm[0][t][0], cm[0][t][2]),
                         fmaxf(cm[1][t][0], cm[1][t][2]));
        float m1 = fmaxf(fmaxf(cm[0][t][1], cm[0][t][3]),
                         fmaxf(cm[1][t][1], cm[1][t][3]));
#pragma unroll
        for (int off = 4; off < 32; off <<= 1) {
            m0 = fmaxf(m0, __shfl_xor_sync(0xffffffffu, m0, off));
            m1 = fmaxf(m1, __shfl_xor_sync(0xffffffffu, m1, off));
        }
        if (lane < 4) {
            const int col = ng * 64 + (t >> 1) * 16 + (t & 1) * 8 + lane * 2;
            wmax[mg * 128 + col]     = m0;
            wmax[mg * 128 + col + 1] = m1;
        }
    }
    __syncthreads();
    if (tid < 128) {
        const float m = fmaxf(fmaxf(wmax[tid], wmax[128 + tid]),
                              fmaxf(wmax[256 + tid], wmax[384 + tid]));
        atomicMax(&g_featmax[sample * 256 + nh * 128 + tid], enc_key(m));
    }

    // tail rows l=256,257 (half==1), this CTA's n-half
    if (half == 1) {
        const int l_idx = tid >> 7;
        const int oc = nh * 128 + (tid & 127);
        const __half* e254 = (const __half*)(sm + EHI_OFF) + 128 * ES;
        const __half* e255 = (const __half*)(sm + EHI_OFF) + 129 * ES;
        const float* W = conv_w + oc * 384;
        float acc = 0.0f;
        if (l_idx == 0) {
#pragma unroll 8
            for (int d = 0; d < 128; d += 2) {
                const float2 w0 = *(const float2*)(W + d);
                const float2 w1 = *(const float2*)(W + 128 + d);
                const float2 ea = __half22float2(*(const __half2*)(e254 + d));
                const float2 eb = __half22float2(*(const __half2*)(e255 + d));
                acc += w0.x * ea.x + w0.y * ea.y + w1.x * eb.x + w1.y * eb.y;
            }
        } else {
#pragma unroll 8
            for (int d = 0; d < 128; d += 2) {
                const float2 w0 = *(const float2*)(W + d);
                const float2 eb = __half22float2(*(const __half2*)(e255 + d));
                acc += w0.x * eb.x + w0.y * eb.y;
            }
        }
        atomicMax(&g_featmax[sample * 256 + oc], enc_key(acc));
    }
}

// ---------------------------------------------------------------------------
// Kernel 2: gi = feat @ w_ih^T + b_ih (coalesced g_Wti)
// ---------------------------------------------------------------------------
__global__ void __launch_bounds__(256) gi_kernel(
    const float* __restrict__ b_ih_f, const float* __restrict__ b_ih_b,
    const float* __restrict__ conv_b)
{
    __shared__ float As[BATCH * OC];
    const int tid = threadIdx.x;
    const int dir = blockIdx.x >> 6;
    const int n   = blockIdx.x & 63;

    for (int i = tid; i < BATCH * OC; i += 256) {
        const unsigned key = g_featmax[(n * BATCH + (i >> 8)) * 256 + (i & 255)];
        const unsigned bits = (key & 0x80000000u) ? (key & 0x7fffffffu) : ~key;
        As[i] = tanhf(conv_b[i & 255] + __uint_as_float(bits));
    }

    const float* bi = dir ? b_ih_b : b_ih_f;
    const float4* W0 = g_Wti + dir * 49152 + tid;
    const float4* W1 = W0 + 64 * 256;
    const float4* W2 = W0 + 128 * 256;

    float acc0[32], acc1[32], acc2[32];
#pragma unroll
    for (int bb = 0; bb < 32; bb++) { acc0[bb] = 0.f; acc1[bb] = 0.f; acc2[bb] = 0.f; }
    __syncthreads();

    for (int k4 = 0; k4 < OC / 4; k4++) {
        const float4 v0 = W0[k4 * 256];
        const float4 v1 = W1[k4 * 256];
        const float4 v2 = W2[k4 * 256];
#pragma unroll
        for (int bb = 0; bb < 32; bb++) {
            const float4 a = *(const float4*)&As[bb * OC + k4 * 4];
            acc0[bb] += v0.x * a.x + v0.y * a.y + v0.z * a.z + v0.w * a.w;
            acc1[bb] += v1.x * a.x + v1.y * a.y + v1.z * a.z + v1.w * a.w;
            acc2[bb] += v2.x * a.x + v2.y * a.y + v2.z * a.z + v2.w * a.w;
        }
    }
    const float bi0 = bi[tid], bi1 = bi[tid + 256], bi2 = bi[tid + 512];
    float* go = g_gi + (size_t)((dir * N_NOTES + n) * BATCH) * 768;
#pragma unroll 4
    for (int bb = 0; bb < 32; bb++) {
        go[bb * 768 +       tid] = acc0[bb] + bi0;
        go[bb * 768 + 256 + tid] = acc1[bb] + bi1;
        go[bb * 768 + 512 + tid] = acc2[bb] + bi2;
    }
}

// ---------------------------------------------------------------------------
// Kernel 3: GRU — cluster of 4 CTAs (n-quarters) per (dir, batch-pair).
// (unchanged: measured 247 us)
// ---------------------------------------------------------------------------
__global__ void __launch_bounds__(1024, 1) __cluster_dims__(4, 1, 1)
gru_kernel(const float* __restrict__ b_hh_f, const float* __restrict__ b_hh_b,
           const float* __restrict__ hidden_state,
           float* __restrict__ out)
{
    __shared__ float h2[2][2][HID];
    __shared__ float red[16][3][2][64];
    const int tid = threadIdx.x;
    const int nq   = blockIdx.x & 3;
    const int cidx = blockIdx.x >> 2;
    const int dir  = cidx >> 4;
    const int bp   = cidx & 15;
    const int b0   = bp * 2;
    const int i    = tid & 63;
    const int ks   = tid >> 6;
    const int ig   = nq * 64 + i;

    const float* bhh = dir ? b_hh_b : b_hh_f;
    const float4* Wb = g_Wth + dir * 49152 + ig;

    if (tid < 512) {
        const int bb = tid >> 8, nn = tid & 255;
        h2[0][bb][nn] = hidden_state[(dir * BATCH + b0 + bb) * HID + nn];
    }
    float bh0 = 0.f, bh1 = 0.f, bh2 = 0.f;
    if (tid < 128) { bh0 = bhh[ig]; bh1 = bhh[ig + 256]; bh2 = bhh[ig + 512]; }
    __syncthreads();
    CLUSTER_BAR();

    for (int s = 0; s < N_NOTES; s++) {
        const int par = s & 1;
        const int n = dir ? (N_NOTES - 1 - s) : s;
        float a0 = 0.f, a1 = 0.f, a2 = 0.f;
        float c0 = 0.f, c1 = 0.f, c2 = 0.f;
#pragma unroll
        for (int j = 0; j < 4; j++) {
            const int k4 = ks * 4 + j;
            const float4 w0 = Wb[(k4      ) * 256];
            const float4 w1 = Wb[(k4 +  64) * 256];
            const float4 w2 = Wb[(k4 + 128) * 256];
            const float4 hA = *(const float4*)&h2[par][0][k4 * 4];
            const float4 hB = *(const float4*)&h2[par][1][k4 * 4];
            a0 += w0.x * hA.x + w0.y * hA.y + w0.z * hA.z + w0.w * hA.w;
            c0 += w0.x * hB.x + w0.y * hB.y + w0.z * hB.z + w0.w * hB.w;
            a1 += w1.x * hA.x + w1.y * hA.y + w1.z * hA.z + w1.w * hA.w;
            c1 += w1.x * hB.x + w1.y * hB.y + w1.z * hB.z + w1.w * hB.w;
            a2 += w2.x * hA.x + w2.y * hA.y + w2.z * hA.z + w2.w * hA.w;
            c2 += w2.x * hB.x + w2.y * hB.y + w2.z * hB.z + w2.w * hB.w;
        }
        red[ks][0][0][i] = a0;  red[ks][0][1][i] = c0;
        red[ks][1][0][i] = a1;  red[ks][1][1][i] = c1;
        red[ks][2][0][i] = a2;  red[ks][2][1][i] = c2;
        __syncthreads();
        if (tid < 128) {
            const int bb = tid >> 6;
            float g0 = bh0, g1 = bh1, g2 = bh2;
#pragma unroll
            for (int q = 0; q < 16; q++) {
                g0 += red[q][0][bb][i];
                g1 += red[q][1][bb][i];
                g2 += red[q][2][bb][i];
            }
            const float* gp = g_gi + (size_t)((dir * N_NOTES + n) * BATCH + b0 + bb) * 768;
            const float r  = 1.0f / (1.0f + expf(-(gp[ig]       + g0)));
            const float z  = 1.0f / (1.0f + expf(-(gp[ig + 256] + g1)));
            const float nn = tanhf(gp[ig + 512] + r * g2);
            const float hn = (1.0f - z) * nn + z * h2[par][bb][ig];
            const unsigned la = (unsigned)__cvta_generic_to_shared(&h2[par ^ 1][bb][ig]);
#pragma unroll
            for (unsigned rk = 0; rk < 4; rk++) dsmem_st(la, rk, hn);
            out[(size_t)(n * BATCH + b0 + bb) * 512 + dir * HID + ig] = hn;
        }
        CLUSTER_BAR();
    }
}

// ---------------------------------------------------------------------------
// Kernel 4: additive attention scores (coalesced g_WAp)
// ---------------------------------------------------------------------------
__global__ void __launch_bounds__(256) attn_kernel(
    const float* __restrict__ out_note,
    const float* __restrict__ bias_note,
    const float* __restrict__ proj_note)
{
    extern __shared__ float As[];
    __shared__ float wred[8][32];
    const int tid = threadIdx.x;
    const int n = blockIdx.x;

    const float* src = out_note + (size_t)n * BATCH * 512;
    for (int i = tid; i < (BATCH * 512) / 4; i += 256)
        ((float4*)As)[i] = ((const float4*)src)[i];

    float attnacc[32];
#pragma unroll
    for (int bb = 0; bb < 32; bb++) attnacc[bb] = 0.0f;
    __syncthreads();

    for (int ee = 0; ee < 2; ee++) {
        const int e = ee * 256 + tid;
        float acc[32];
#pragma unroll
        for (int bb = 0; bb < 32; bb++) acc[bb] = 0.0f;
        for (int d4 = 0; d4 < 128; d4++) {
            const float4 wv = g_WAp[d4 * 512 + e];
#pragma unroll
            for (int bb = 0; bb < 32; bb++) {
                const float4 a = *(const float4*)&As[bb * 512 + d4 * 4];
                acc[bb] += wv.x * a.x + wv.y * a.y + wv.z * a.z + wv.w * a.w;
            }
        }
        const float be = bias_note[e], pe = proj_note[e];
#pragma unroll
        for (int bb = 0; bb < 32; bb++)
            attnacc[bb] += tanhf(acc[bb] + be) * pe;
    }
#pragma unroll
    for (int off = 16; off; off >>= 1)
#pragma unroll
        for (int bb = 0; bb < 32; bb++)
            attnacc[bb] += __shfl_xor_sync(0xffffffffu, attnacc[bb], off);
    const int wid = tid >> 5, lane = tid & 31;
    if (lane == 0)
#pragma unroll
        for (int bb = 0; bb < 32; bb++) wred[wid][bb] = attnacc[bb];
    __syncthreads();
    if (tid < 32) {
        float s = 0.0f;
#pragma unroll
        for (int w = 0; w < 8; w++) s += wred[w][tid];
        g_attn[n * BATCH + tid] = s;
    }
}

// ---------------------------------------------------------------------------
// Kernel 5: softmax + weighted sum + final linear. CTA per b.
// ---------------------------------------------------------------------------
__global__ void __launch_bounds__(256) final_kernel(
    const float* __restrict__ out_note,
    const float* __restrict__ lin_w,
    const float* __restrict__ lin_b,
    float* __restrict__ out)
{
    __shared__ float sa[64];
    __shared__ float vec[512];
    __shared__ float stats[2];
    const int tid = threadIdx.x;
    const int b = blockIdx.x;

    if (tid < 64) sa[tid] = g_attn[tid * BATCH + b];
    __syncthreads();
    if (tid < 32) {
        const float v0 = sa[tid], v1 = sa[tid + 32];
        float m = fmaxf(v0, v1);
#pragma unroll
        for (int o = 16; o; o >>= 1) m = fmaxf(m, __shfl_xor_sync(0xffffffffu, m, o));
        float s = expf(v0 - m) + expf(v1 - m);
#pragma unroll
        for (int o = 16; o; o >>= 1) s += __shfl_xor_sync(0xffffffffu, s, o);
        if (tid == 0) { stats[0] = m; stats[1] = s; }
    }
    __syncthreads();
    if (tid < 64) {
        const float nv = expf(sa[tid] - stats[0]) / stats[1];
        sa[tid] = nv;
        out[OFF_NORM + b * 64 + tid] = nv;
    }
    __syncthreads();
#pragma unroll
    for (int dd = 0; dd < 2; dd++) {
        const int d = dd * 256 + tid;
        float acc = 0.0f;
#pragma unroll 8
        for (int n = 0; n < 64; n++)
            acc += sa[n] * out_note[(size_t)(n * BATCH + b) * 512 + d];
        vec[d] = acc;
        out[OFF_VEC + b * 512 + d] = acc;
    }
    __syncthreads();
    if (tid < 64) {
        const int c = tid >> 5, lane = tid & 31;
        float p = 0.0f;
#pragma unroll 4
        for (int i = lane; i < 512; i += 32) p += lin_w[c * 512 + i] * vec[i];
#pragma unroll
        for (int o = 16; o; o >>= 1) p += __shfl_xor_sync(0xffffffffu, p, o);
        if (lane == 0) out[OFF_FIN + b * 2 + c] = p + lin_b[c];
    }
}

// ---------------------------------------------------------------------------
// Launcher — conv is the 4th launch (profiler captures launch #4)
// ---------------------------------------------------------------------------
extern "C" void kernel_launch(void* const* d_in, const int* in_sizes, int n_in,
                              void* d_out, int out_size)
{
    (void)in_sizes; (void)n_in; (void)out_size;
    const int*   mini_batch = (const int*)d_in[0];
    const float* hidden     = (const float*)d_in[1];
    const float* embed      = (const float*)d_in[2];
    const float* conv_w     = (const float*)d_in[3];
    const float* conv_b     = (const float*)d_in[4];
    const float* w_ih_f     = (const float*)d_in[5];
    const float* w_hh_f     = (const float*)d_in[6];
    const float* b_ih_f     = (const float*)d_in[7];
    const float* b_hh_f     = (const float*)d_in[8];
    const float* w_ih_b     = (const float*)d_in[9];
    const float* w_hh_b     = (const float*)d_in[10];
    const float* b_ih_b     = (const float*)d_in[11];
    const float* b_hh_b     = (const float*)d_in[12];
    const float* W_note     = (const float*)d_in[13];
    const float* bias_note  = (const float*)d_in[14];
    const float* proj_note  = (const float*)d_in[15];
    const float* lin_w      = (const float*)d_in[16];
    const float* lin_b      = (const float*)d_in[17];
    float* out = (float*)d_out;

    cudaFuncSetAttribute(conv_mma_kernel,
                         cudaFuncAttributeMaxDynamicSharedMemorySize, CONV_SMEM);
    cudaFuncSetAttribute(attn_kernel,
                         cudaFuncAttributeMaxDynamicSharedMemorySize, 65536);

    prep_a_kernel<<<2048, 256>>>(conv_w);
    prep_b_kernel<<<768, 256>>>(w_hh_f, w_hh_b, w_ih_f, w_ih_b);
    prep_c_kernel<<<256, 256>>>(W_note);
    conv_mma_kernel<<<N_NOTES * BATCH * 4, 256, CONV_SMEM>>>(mini_batch, embed, conv_w);
    gi_kernel<<<128, 256>>>(b_ih_f, b_ih_b, conv_b);
    gru_kernel<<<128, 1024>>>(b_hh_f, b_hh_b, hidden, out);
    attn_kernel<<<64, 256, 65536>>>(out, bias_note, proj_note);
    final_kernel<<<32, 256>>>(out, lin_w, lin_b, out);
}

// round 16
// speedup vs baseline: 2.5600x; 1.0306x over previous
#include <cuda_runtime.h>
#include <cuda_fp16.h>
#include <math.h>

// ---------------------------------------------------------------------------
// Problem constants
// ---------------------------------------------------------------------------
#define N_NOTES   64
#define N_WORDS   256
#define BATCH     32
#define WDIM      128
#define OC        256
#define HID       256

// Output layout (float32)
#define OFF_NORM 1048576
#define OFF_VEC  1050624
#define OFF_FIN  1067008

// ---------------------------------------------------------------------------
// Scratch (device globals)
// ---------------------------------------------------------------------------
__device__ unsigned int g_featmax[N_NOTES * BATCH * OC];
__device__ float        g_gi[2 * N_NOTES * BATCH * 3 * HID];
__device__ float        g_attn[N_NOTES * BATCH];
// conv W fp16, repacked per n-half: [nhalf][k=384][col=136 halfs]
__device__ __half       g_Bp[2][384][136];
// GRU weights, coalesced: [dir][(gate*64+k4)*256 + n] = float4 over k
__device__ float4       g_Wth[2 * 49152];   // w_hh
__device__ float4       g_Wti[2 * 49152];   // w_ih
// W_note coalesced: [d4*512 + e] = float4 over d
__device__ float4       g_WAp[65536];

// ---------------------------------------------------------------------------
// PTX helpers
// ---------------------------------------------------------------------------
__device__ __forceinline__ void ldm_x4(unsigned* r, unsigned addr) {
    asm volatile("ldmatrix.sync.aligned.m8n8.x4.shared.b16 {%0,%1,%2,%3},[%4];"
        : "=r"(r[0]), "=r"(r[1]), "=r"(r[2]), "=r"(r[3]) : "r"(addr));
}
__device__ __forceinline__ void ldm_x4t(unsigned* r, unsigned addr) {
    asm volatile("ldmatrix.sync.aligned.m8n8.x4.trans.shared.b16 {%0,%1,%2,%3},[%4];"
        : "=r"(r[0]), "=r"(r[1]), "=r"(r[2]), "=r"(r[3]) : "r"(addr));
}
__device__ __forceinline__ void mma16816(float* c, const unsigned* a, const unsigned* b) {
    asm volatile("mma.sync.aligned.m16n8k16.row.col.f32.f16.f16.f32 "
        "{%0,%1,%2,%3},{%4,%5,%6,%7},{%8,%9},{%0,%1,%2,%3};"
        : "+f"(c[0]), "+f"(c[1]), "+f"(c[2]), "+f"(c[3])
        : "r"(a[0]), "r"(a[1]), "r"(a[2]), "r"(a[3]), "r"(b[0]), "r"(b[1]));
}
__device__ __forceinline__ void cp16(unsigned dst, const void* src) {
    asm volatile("cp.async.cg.shared.global [%0],[%1],16;" :: "r"(dst), "l"(src));
}
__device__ __forceinline__ void cp_commit() { asm volatile("cp.async.commit_group;"); }
template<int N> __device__ __forceinline__ void cp_wait() {
    asm volatile("cp.async.wait_group %0;" :: "n"(N));
}
__device__ __forceinline__ unsigned enc_key(float m) {
    unsigned bits = __float_as_uint(m);
    return (bits & 0x80000000u) ? ~bits : (bits | 0x80000000u);
}
__device__ __forceinline__ void dsmem_st(unsigned laddr, unsigned rank, float v) {
    unsigned ra;
    asm volatile("mapa.shared::cluster.u32 %0, %1, %2;" : "=r"(ra) : "r"(laddr), "r"(rank));
    asm volatile("st.shared::cluster.f32 [%0], %1;" :: "r"(ra), "f"(v) : "memory");
}
#define CLUSTER_BAR() do { \
    asm volatile("barrier.cluster.arrive.aligned;" ::: "memory"); \
    asm volatile("barrier.cluster.wait.aligned;" ::: "memory"); } while (0)

// ---------------------------------------------------------------------------
// Kernel 0a: featmax init + conv W fp16 repack
// ---------------------------------------------------------------------------
__global__ void __launch_bounds__(256) prep_a_kernel(const float* __restrict__ conv_w)
{
    const int blk = blockIdx.x, tid = threadIdx.x;
    g_featmax[blk * 256 + tid] = 0u;
    if (blk < 384) {
        const int k = blk, n = tid;
        g_Bp[n >> 7][k][n & 127] = __float2half(conv_w[n * 384 + k]);
    }
}

// ---------------------------------------------------------------------------
// Kernel 0b: GRU weight repack (w_hh, w_ih)
// ---------------------------------------------------------------------------
__global__ void __launch_bounds__(256) prep_b_kernel(
    const float* __restrict__ w_hh_f, const float* __restrict__ w_hh_b,
    const float* __restrict__ w_ih_f, const float* __restrict__ w_ih_b)
{
    const int idx = blockIdx.x * 256 + threadIdx.x;
    const int which = idx / 98304;
    const int r = idx % 98304;
    const int n = r & 255, k4 = (r >> 8) & 63, gd = r >> 14;
    const int dir = gd / 3, gate = gd % 3;
    const float* W = which ? (dir ? w_ih_b : w_ih_f)
                           : (dir ? w_hh_b : w_hh_f);
    const float* src = W + (gate * 256 + n) * 256 + k4 * 4;
    const float4 v = make_float4(src[0], src[1], src[2], src[3]);
    float4* dst = which ? g_Wti : g_Wth;
    dst[dir * 49152 + (gate * 64 + k4) * 256 + n] = v;
}

// ---------------------------------------------------------------------------
// Kernel 0c: W_note repack
// ---------------------------------------------------------------------------
__global__ void __launch_bounds__(256) prep_c_kernel(const float* __restrict__ W_note)
{
    const int idx = blockIdx.x * 256 + threadIdx.x;
    const int e = idx & 511, d4 = idx >> 9;
    g_WAp[d4 * 512 + e] = make_float4(
        W_note[(d4 * 4 + 0) * 512 + e], W_note[(d4 * 4 + 1) * 512 + e],
        W_note[(d4 * 4 + 2) * 512 + e], W_note[(d4 * 4 + 3) * 512 + e]);
}

// ---------------------------------------------------------------------------
// Kernel 1: conv — single-term fp16 HMMA; CTA = (sample, l-half, n-half).
// 256 threads, warp tile m32 x n64, 2 CTAs/SM. 6 k-chunks of 64 (cp.async.cg,
// double-buffered); B-LDSMs hoisted ahead of the MMA block (r9-proven shape).
// ---------------------------------------------------------------------------
#define ES      136
#define EROWS   132
#define BSH     136
#define BCH     17408      // 64 k-rows * 272B
#define EHI_OFF 0
#define B_OFF   35904      // 2 stages x 17408 -> ends 70720
#define WMAX_OFF 70720     // 4 x 128 floats -> 72768
#define TOK_OFF  72768     // 132 ints -> 73296
#define CONV_SMEM 73344

__global__ void __launch_bounds__(256, 2) conv_mma_kernel(
    const int*   __restrict__ mini_batch,
    const float* __restrict__ embed,
    const float* __restrict__ conv_w)
{
    extern __shared__ char sm[];
    const unsigned smu = (unsigned)__cvta_generic_to_shared(sm);
    const int tid = threadIdx.x, lane = tid & 31, w = tid >> 5;
    const int mg = w >> 1;
    const int ng = w & 1;
    const int sample = blockIdx.x >> 2;
    const int half   = (blockIdx.x >> 1) & 1;
    const int nh     = blockIdx.x & 1;
    const int l0     = half << 7;
    const int n = sample >> 5, b = sample & 31;

    int* tok = (int*)(sm + TOK_OFF);
    const char* srcB = (const char*)&g_Bp[nh][0][0];

    // prefetch B chunks 0,1 (k rows 0..63, 64..127)
    for (int i = tid; i < BCH / 16; i += 256)
        cp16(smu + B_OFF + i * 16, srcB + i * 16);
    cp_commit();
    for (int i = tid; i < BCH / 16; i += 256)
        cp16(smu + B_OFF + BCH + i * 16, srcB + BCH + i * 16);
    cp_commit();

    if (tid < EROWS) {
        const int word = l0 + tid - 2;
        tok[tid] = (word >= 0 && word < N_WORDS)
                 ? mini_batch[(n * N_WORDS + word) * BATCH + b] : -1;
    }
    __syncthreads();

    // build E (fp16)  [r14-proven uint2 path]
    for (int i = tid; i < EROWS * 32; i += 256) {
        const int row = i >> 5, q = i & 31;
        const int t = tok[row];
        float4 v;
        if (t >= 0) v = *(const float4*)(embed + (size_t)t * WDIM + q * 4);
        else        v = make_float4(0.f, 0.f, 0.f, 0.f);
        __half2 hp0 = __halves2half2(__float2half(v.x), __float2half(v.y));
        __half2 hp1 = __halves2half2(__float2half(v.z), __float2half(v.w));
        *(uint2*)(sm + EHI_OFF + (unsigned)(row * ES + q * 4) * 2) =
            make_uint2(*(unsigned*)&hp0, *(unsigned*)&hp1);
    }

    float cm[2][8][4];
#pragma unroll
    for (int i = 0; i < 2; i++)
#pragma unroll
        for (int j = 0; j < 8; j++)
#pragma unroll
            for (int r = 0; r < 4; r++) cm[i][j][r] = 0.0f;
    __syncthreads();

    // ---- main loop: 6 k-chunks of 64 ----
    for (int c = 0; c < 6; c++) {
        const int stage = c & 1;
        if (c < 5) cp_wait<1>(); else cp_wait<0>();
        __syncthreads();

#pragma unroll
        for (int h = 0; h < 4; h++) {
            const int k0 = c * 64 + h * 16;
            const int seg = k0 >> 7, kk = k0 & 127;
            const unsigned acol = kk + ((lane >> 4) << 3);
            unsigned ahi[2][4];
#pragma unroll
            for (int mt = 0; mt < 2; mt++) {
                const unsigned aoff =
                    ((mg * 32 + mt * 16 + (lane & 15) + seg) * ES + acol) * 2;
                ldm_x4(ahi[mt], smu + EHI_OFF + aoff);
            }
            const unsigned brow = (h << 4) + (lane & 15);
            unsigned bh[4][4];
#pragma unroll
            for (int nn = 0; nn < 4; nn++) {
                const unsigned bcol = ng * 64 + nn * 16 + ((lane >> 4) << 3);
                ldm_x4t(bh[nn], smu + B_OFF + stage * BCH + brow * (BSH * 2) + bcol * 2);
            }
#pragma unroll
            for (int nn = 0; nn < 4; nn++)
#pragma unroll
                for (int mt = 0; mt < 2; mt++) {
                    mma16816(cm[mt][nn * 2],     ahi[mt], bh[nn]);
                    mma16816(cm[mt][nn * 2 + 1], ahi[mt], bh[nn] + 2);
                }
        }
        __syncthreads();
        if (c + 2 < 6) {
            const int coff = (c + 2) * BCH;
            for (int i = tid; i < BCH / 16; i += 256)
                cp16(smu + B_OFF + stage * BCH + i * 16, srcB + coff + i * 16);
            cp_commit();
        }
    }

    float* wmax = (float*)(sm + WMAX_OFF);
#pragma unroll
    for (int t = 0; t < 8; t++) {
        float m0 = fmaxf(fmaxf(cm[0][t][0], cm[0][t][2]),
                         fmaxf(cm[1][t][0], cm[1][t][2]));
        float m1 = fmaxf(fmaxf(cm[0][t][1], cm[0][t][3]),
                         fmaxf(cm[1][t][1], cm[1][t][3]));
#pragma unroll
        for (int off = 4; off < 32; off <<= 1) {
            m0 = fmaxf(m0, __shfl_xor_sync(0xffffffffu, m0, off));
            m1 = fmaxf(m1, __shfl_xor_sync(0xffffffffu, m1, off));
        }
        if (lane < 4) {
            const int col = ng * 64 + (t >> 1) * 16 + (t & 1) * 8 + lane * 2;
            wmax[mg * 128 + col]     = m0;
            wmax[mg * 128 + col + 1] = m1;
        }
    }
    __syncthreads();
    if (tid < 128) {
        const float m = fmaxf(fmaxf(wmax[tid], wmax[128 + tid]),
                              fmaxf(wmax[256 + tid], wmax[384 + tid]));
        atomicMax(&g_featmax[sample * 256 + nh * 128 + tid], enc_key(m));
    }

    // tail rows l=256,257 (half==1), this CTA's n-half
    if (half == 1) {
        const int l_idx = tid >> 7;
        const int oc = nh * 128 + (tid & 127);
        const __half* e254 = (const __half*)(sm + EHI_OFF) + 128 * ES;
        const __half* e255 = (const __half*)(sm + EHI_OFF) + 129 * ES;
        const float* W = conv_w + oc * 384;
        float acc = 0.0f;
        if (l_idx == 0) {
#pragma unroll 8
            for (int d = 0; d < 128; d += 2) {
                const float2 w0 = *(const float2*)(W + d);
                const float2 w1 = *(const float2*)(W + 128 + d);
                const float2 ea = __half22float2(*(const __half2*)(e254 + d));
                const float2 eb = __half22float2(*(const __half2*)(e255 + d));
                acc += w0.x * ea.x + w0.y * ea.y + w1.x * eb.x + w1.y * eb.y;
            }
        } else {
#pragma unroll 8
            for (int d = 0; d < 128; d += 2) {
                const float2 w0 = *(const float2*)(W + d);
                const float2 eb = __half22float2(*(const __half2*)(e255 + d));
                acc += w0.x * eb.x + w0.y * eb.y;
            }
        }
        atomicMax(&g_featmax[sample * 256 + oc], enc_key(acc));
    }
}

// ---------------------------------------------------------------------------
// Kernel 2: gi = feat @ w_ih^T + b_ih (coalesced g_Wti)
// ---------------------------------------------------------------------------
__global__ void __launch_bounds__(256) gi_kernel(
    const float* __restrict__ b_ih_f, const float* __restrict__ b_ih_b,
    const float* __restrict__ conv_b)
{
    __shared__ float As[BATCH * OC];
    const int tid = threadIdx.x;
    const int dir = blockIdx.x >> 6;
    const int n   = blockIdx.x & 63;

    for (int i = tid; i < BATCH * OC; i += 256) {
        const unsigned key = g_featmax[(n * BATCH + (i >> 8)) * 256 + (i & 255)];
        const unsigned bits = (key & 0x80000000u) ? (key & 0x7fffffffu) : ~key;
        As[i] = tanhf(conv_b[i & 255] + __uint_as_float(bits));
    }

    const float* bi = dir ? b_ih_b : b_ih_f;
    const float4* W0 = g_Wti + dir * 49152 + tid;
    const float4* W1 = W0 + 64 * 256;
    const float4* W2 = W0 + 128 * 256;

    float acc0[32], acc1[32], acc2[32];
#pragma unroll
    for (int bb = 0; bb < 32; bb++) { acc0[bb] = 0.f; acc1[bb] = 0.f; acc2[bb] = 0.f; }
    __syncthreads();

    for (int k4 = 0; k4 < OC / 4; k4++) {
        const float4 v0 = W0[k4 * 256];
        const float4 v1 = W1[k4 * 256];
        const float4 v2 = W2[k4 * 256];
#pragma unroll
        for (int bb = 0; bb < 32; bb++) {
            const float4 a = *(const float4*)&As[bb * OC + k4 * 4];
            acc0[bb] += v0.x * a.x + v0.y * a.y + v0.z * a.z + v0.w * a.w;
            acc1[bb] += v1.x * a.x + v1.y * a.y + v1.z * a.z + v1.w * a.w;
            acc2[bb] += v2.x * a.x + v2.y * a.y + v2.z * a.z + v2.w * a.w;
        }
    }
    const float bi0 = bi[tid], bi1 = bi[tid + 256], bi2 = bi[tid + 512];
    float* go = g_gi + (size_t)((dir * N_NOTES + n) * BATCH) * 768;
#pragma unroll 4
    for (int bb = 0; bb < 32; bb++) {
        go[bb * 768 +       tid] = acc0[bb] + bi0;
        go[bb * 768 + 256 + tid] = acc1[bb] + bi1;
        go[bb * 768 + 512 + tid] = acc2[bb] + bi2;
    }
}

// ---------------------------------------------------------------------------
// Kernel 3: GRU — cluster of 4 CTAs (n-quarters) per (dir, batch-pair).
// (unchanged: measured 247 us)
// ---------------------------------------------------------------------------
__global__ void __launch_bounds__(1024, 1) __cluster_dims__(4, 1, 1)
gru_kernel(const float* __restrict__ b_hh_f, const float* __restrict__ b_hh_b,
           const float* __restrict__ hidden_state,
           float* __restrict__ out)
{
    __shared__ float h2[2][2][HID];
    __shared__ float red[16][3][2][64];
    const int tid = threadIdx.x;
    const int nq   = blockIdx.x & 3;
    const int cidx = blockIdx.x >> 2;
    const int dir  = cidx >> 4;
    const int bp   = cidx & 15;
    const int b0   = bp * 2;
    const int i    = tid & 63;
    const int ks   = tid >> 6;
    const int ig   = nq * 64 + i;

    const float* bhh = dir ? b_hh_b : b_hh_f;
    const float4* Wb = g_Wth + dir * 49152 + ig;

    if (tid < 512) {
        const int bb = tid >> 8, nn = tid & 255;
        h2[0][bb][nn] = hidden_state[(dir * BATCH + b0 + bb) * HID + nn];
    }
    float bh0 = 0.f, bh1 = 0.f, bh2 = 0.f;
    if (tid < 128) { bh0 = bhh[ig]; bh1 = bhh[ig + 256]; bh2 = bhh[ig + 512]; }
    __syncthreads();
    CLUSTER_BAR();

    for (int s = 0; s < N_NOTES; s++) {
        const int par = s & 1;
        const int n = dir ? (N_NOTES - 1 - s) : s;
        float a0 = 0.f, a1 = 0.f, a2 = 0.f;
        float c0 = 0.f, c1 = 0.f, c2 = 0.f;
#pragma unroll
        for (int j = 0; j < 4; j++) {
            const int k4 = ks * 4 + j;
            const float4 w0 = Wb[(k4      ) * 256];
            const float4 w1 = Wb[(k4 +  64) * 256];
            const float4 w2 = Wb[(k4 + 128) * 256];
            const float4 hA = *(const float4*)&h2[par][0][k4 * 4];
            const float4 hB = *(const float4*)&h2[par][1][k4 * 4];
            a0 += w0.x * hA.x + w0.y * hA.y + w0.z * hA.z + w0.w * hA.w;
            c0 += w0.x * hB.x + w0.y * hB.y + w0.z * hB.z + w0.w * hB.w;
            a1 += w1.x * hA.x + w1.y * hA.y + w1.z * hA.z + w1.w * hA.w;
            c1 += w1.x * hB.x + w1.y * hB.y + w1.z * hB.z + w1.w * hB.w;
            a2 += w2.x * hA.x + w2.y * hA.y + w2.z * hA.z + w2.w * hA.w;
            c2 += w2.x * hB.x + w2.y * hB.y + w2.z * hB.z + w2.w * hB.w;
        }
        red[ks][0][0][i] = a0;  red[ks][0][1][i] = c0;
        red[ks][1][0][i] = a1;  red[ks][1][1][i] = c1;
        red[ks][2][0][i] = a2;  red[ks][2][1][i] = c2;
        __syncthreads();
        if (tid < 128) {
            const int bb = tid >> 6;
            float g0 = bh0, g1 = bh1, g2 = bh2;
#pragma unroll
            for (int q = 0; q < 16; q++) {
                g0 += red[q][0][bb][i];
                g1 += red[q][1][bb][i];
                g2 += red[q][2][bb][i];
            }
            const float* gp = g_gi + (size_t)((dir * N_NOTES + n) * BATCH + b0 + bb) * 768;
            const float r  = 1.0f / (1.0f + expf(-(gp[ig]       + g0)));
            const float z  = 1.0f / (1.0f + expf(-(gp[ig + 256] + g1)));
            const float nn = tanhf(gp[ig + 512] + r * g2);
            const float hn = (1.0f - z) * nn + z * h2[par][bb][ig];
            const unsigned la = (unsigned)__cvta_generic_to_shared(&h2[par ^ 1][bb][ig]);
#pragma unroll
            for (unsigned rk = 0; rk < 4; rk++) dsmem_st(la, rk, hn);
            out[(size_t)(n * BATCH + b0 + bb) * 512 + dir * HID + ig] = hn;
        }
        CLUSTER_BAR();
    }
}

// ---------------------------------------------------------------------------
// Kernel 4: additive attention scores (coalesced g_WAp)
// ---------------------------------------------------------------------------
__global__ void __launch_bounds__(256) attn_kernel(
    const float* __restrict__ out_note,
    const float* __restrict__ bias_note,
    const float* __restrict__ proj_note)
{
    extern __shared__ float As[];
    __shared__ float wred[8][32];
    const int tid = threadIdx.x;
    const int n = blockIdx.x;

    const float* src = out_note + (size_t)n * BATCH * 512;
    for (int i = tid; i < (BATCH * 512) / 4; i += 256)
        ((float4*)As)[i] = ((const float4*)src)[i];

    float attnacc[32];
#pragma unroll
    for (int bb = 0; bb < 32; bb++) attnacc[bb] = 0.0f;
    __syncthreads();

    for (int ee = 0; ee < 2; ee++) {
        const int e = ee * 256 + tid;
        float acc[32];
#pragma unroll
        for (int bb = 0; bb < 32; bb++) acc[bb] = 0.0f;
        for (int d4 = 0; d4 < 128; d4++) {
            const float4 wv = g_WAp[d4 * 512 + e];
#pragma unroll
            for (int bb = 0; bb < 32; bb++) {
                const float4 a = *(const float4*)&As[bb * 512 + d4 * 4];
                acc[bb] += wv.x * a.x + wv.y * a.y + wv.z * a.z + wv.w * a.w;
            }
        }
        const float be = bias_note[e], pe = proj_note[e];
#pragma unroll
        for (int bb = 0; bb < 32; bb++)
            attnacc[bb] += tanhf(acc[bb] + be) * pe;
    }
#pragma unroll
    for (int off = 16; off; off >>= 1)
#pragma unroll
        for (int bb = 0; bb < 32; bb++)
            attnacc[bb] += __shfl_xor_sync(0xffffffffu, attnacc[bb], off);
    const int wid = tid >> 5, lane = tid & 31;
    if (lane == 0)
#pragma unroll
        for (int bb = 0; bb < 32; bb++) wred[wid][bb] = attnacc[bb];
    __syncthreads();
    if (tid < 32) {
        float s = 0.0f;
#pragma unroll
        for (int w = 0; w < 8; w++) s += wred[w][tid];
        g_attn[n * BATCH + tid] = s;
    }
}

// ---------------------------------------------------------------------------
// Kernel 5: softmax + weighted sum + final linear. CTA per b.
// ---------------------------------------------------------------------------
__global__ void __launch_bounds__(256) final_kernel(
    const float* __restrict__ out_note,
    const float* __restrict__ lin_w,
    const float* __restrict__ lin_b,
    float* __restrict__ out)
{
    __shared__ float sa[64];
    __shared__ float vec[512];
    __shared__ float stats[2];
    const int tid = threadIdx.x;
    const int b = blockIdx.x;

    if (tid < 64) sa[tid] = g_attn[tid * BATCH + b];
    __syncthreads();
    if (tid < 32) {
        const float v0 = sa[tid], v1 = sa[tid + 32];
        float m = fmaxf(v0, v1);
#pragma unroll
        for (int o = 16; o; o >>= 1) m = fmaxf(m, __shfl_xor_sync(0xffffffffu, m, o));
        float s = expf(v0 - m) + expf(v1 - m);
#pragma unroll
        for (int o = 16; o; o >>= 1) s += __shfl_xor_sync(0xffffffffu, s, o);
        if (tid == 0) { stats[0] = m; stats[1] = s; }
    }
    __syncthreads();
    if (tid < 64) {
        const float nv = expf(sa[tid] - stats[0]) / stats[1];
        sa[tid] = nv;
        out[OFF_NORM + b * 64 + tid] = nv;
    }
    __syncthreads();
#pragma unroll
    for (int dd = 0; dd < 2; dd++) {
        const int d = dd * 256 + tid;
        float acc = 0.0f;
#pragma unroll 8
        for (int n = 0; n < 64; n++)
            acc += sa[n] * out_note[(size_t)(n * BATCH + b) * 512 + d];
        vec[d] = acc;
        out[OFF_VEC + b * 512 + d] = acc;
    }
    __syncthreads();
    if (tid < 64) {
        const int c = tid >> 5, lane = tid & 31;
        float p = 0.0f;
#pragma unroll 4
        for (int i = lane; i < 512; i += 32) p += lin_w[c * 512 + i] * vec[i];
#pragma unroll
        for (int o = 16; o; o >>= 1) p += __shfl_xor_sync(0xffffffffu, p, o);
        if (lane == 0) out[OFF_FIN + b * 2 + c] = p + lin_b[c];
    }
}

// ---------------------------------------------------------------------------
// Launcher — conv is the 4th launch (profiler captures launch #4)
// ---------------------------------------------------------------------------
extern "C" void kernel_launch(void* const* d_in, const int* in_sizes, int n_in,
                              void* d_out, int out_size)
{
    (void)in_sizes; (void)n_in; (void)out_size;
    const int*   mini_batch = (const int*)d_in[0];
    const float* hidden     = (const float*)d_in[1];
    const float* embed      = (const float*)d_in[2];
    const float* conv_w     = (const float*)d_in[3];
    const float* conv_b     = (const float*)d_in[4];
    const float* w_ih_f     = (const float*)d_in[5];
    const float* w_hh_f     = (const float*)d_in[6];
    const float* b_ih_f     = (const float*)d_in[7];
    const float* b_hh_f     = (const float*)d_in[8];
    const float* w_ih_b     = (const float*)d_in[9];
    const float* w_hh_b     = (const float*)d_in[10];
    const float* b_ih_b     = (const float*)d_in[11];
    const float* b_hh_b     = (const float*)d_in[12];
    const float* W_note     = (const float*)d_in[13];
    const float* bias_note  = (const float*)d_in[14];
    const float* proj_note  = (const float*)d_in[15];
    const float* lin_w      = (const float*)d_in[16];
    const float* lin_b      = (const float*)d_in[17];
    float* out = (float*)d_out;

    cudaFuncSetAttribute(conv_mma_kernel,
                         cudaFuncAttributeMaxDynamicSharedMemorySize, CONV_SMEM);
    cudaFuncSetAttribute(attn_kernel,
                         cudaFuncAttributeMaxDynamicSharedMemorySize, 65536);

    prep_a_kernel<<<2048, 256>>>(conv_w);
    prep_b_kernel<<<768, 256>>>(w_hh_f, w_hh_b, w_ih_f, w_ih_b);
    prep_c_kernel<<<256, 256>>>(W_note);
    conv_mma_kernel<<<N_NOTES * BATCH * 4, 256, CONV_SMEM>>>(mini_batch, embed, conv_w);
    gi_kernel<<<128, 256>>>(b_ih_f, b_ih_b, conv_b);
    gru_kernel<<<128, 1024>>>(b_hh_f, b_hh_b, hidden, out);
    attn_kernel<<<64, 256, 65536>>>(out, bias_note, proj_note);
    final_kernel<<<32, 256>>>(out, lin_w, lin_b, out);
}